// round 12
// baseline (speedup 1.0000x reference)
#include <cuda_runtime.h>
#include <cuda_fp16.h>
#include <cstdint>
#include <cstddef>

#define DI __device__ __forceinline__
static const int D_DIM = 512;
#define MAXN 32768
#define MAXK 1024
#define NBN  8

extern "C" __device__ float __nv_logf(float);

// Scratch: fp16 hi/mid fragment-packed operands
__device__ uint32_t g_xf[(size_t)2048 * 32 * 256];  // 64MB: A blocks (mt,kt16): [hi 32x16B | mid 32x16B]
__device__ uint32_t g_cf[(size_t)128 * 32 * 128];   //  2MB: B blocks (nt,kt16): lane -> {b0h,b1h,b0m,b1m}
__device__ float g_pm[(size_t)MAXN * NBN];
__device__ int   g_pi[(size_t)MAXN * NBN];
__device__ float g_ps[(size_t)MAXN * NBN];

// ---------------------------------------------------------------------------
// Threefry-2x32 (exact JAX, partitionable mode)
// ---------------------------------------------------------------------------
__host__ __device__ inline uint32_t rotl32(uint32_t x, int r) {
    return (x << r) | (x >> (32 - r));
}
__host__ __device__ inline void threefry2x32(uint32_t k0, uint32_t k1,
                                             uint32_t& x0, uint32_t& x1) {
    uint32_t k2 = k0 ^ k1 ^ 0x1BD11BDAu;
    x0 += k0; x1 += k1;
#define TFR(r) { x0 += x1; x1 = rotl32(x1, r); x1 ^= x0; }
    TFR(13) TFR(15) TFR(26) TFR(6)
    x0 += k1; x1 += k2 + 1u;
    TFR(17) TFR(29) TFR(16) TFR(24)
    x0 += k2; x1 += k0 + 2u;
    TFR(13) TFR(15) TFR(26) TFR(6)
    x0 += k0; x1 += k1 + 3u;
    TFR(17) TFR(29) TFR(16) TFR(24)
    x0 += k1; x1 += k2 + 4u;
    TFR(13) TFR(15) TFR(26) TFR(6)
    x0 += k2; x1 += k0 + 5u;
#undef TFR
}
DI uint32_t tf_bits(uint32_t k0, uint32_t k1, uint32_t i) {
    uint32_t x0 = 0u, x1 = i;
    threefry2x32(k0, k1, x0, x1);
    return x0 ^ x1;
}
#define TINYF 1.17549435e-38f
DI float gumbel_from_bits(uint32_t bits) {
    float u = __uint_as_float((bits >> 9) | 0x3f800000u) - 1.0f;
    float r = fmaxf(TINYF, u + TINYF);
    return -__nv_logf(-__nv_logf(r));
}
DI float expg_from_bits(uint32_t bits) {
    float u = __uint_as_float((bits >> 9) | 0x3f800000u) - 1.0f;
    float r = fmaxf(TINYF, u + TINYF);
    return -__fdividef(1.0f, __nv_logf(r));
}

// ---------------------------------------------------------------------------
// low-level helpers
// ---------------------------------------------------------------------------
DI uint32_t smem_u32(const void* p) {
    uint32_t a;
    asm("{ .reg .u64 t; cvta.to.shared.u64 t, %1; cvt.u32.u64 %0, t; }"
        : "=r"(a) : "l"(p));
    return a;
}
// split x,y into fp16 hi pair + fp16 mid (residual) pair, packed half2
DI void f16_split2(float x, float y, uint32_t& hi, uint32_t& mi) {
    __half xh = __float2half_rn(x), yh = __float2half_rn(y);
    float xr = x - __half2float(xh), yr = y - __half2float(yh);
    __half xm = __float2half_rn(xr), ym = __float2half_rn(yr);
    hi = (uint32_t)__half_as_ushort(xh) | ((uint32_t)__half_as_ushort(yh) << 16);
    mi = (uint32_t)__half_as_ushort(xm) | ((uint32_t)__half_as_ushort(ym) << 16);
}
DI void cp16(uint32_t saddr, const void* g) {
    asm volatile("cp.async.cg.shared.global [%0], [%1], 16;"
                 :: "r"(saddr), "l"(g) : "memory");
}
#define CP_COMMIT() asm volatile("cp.async.commit_group;" ::: "memory")
#define CP_WAIT1()  asm volatile("cp.async.wait_group 1;" ::: "memory")
#define CP_WAIT0()  asm volatile("cp.async.wait_group 0;" ::: "memory")
DI void lds128(uint32_t* r, uint32_t addr) {
    asm volatile("ld.shared.v4.b32 {%0,%1,%2,%3}, [%4];"
        : "=r"(r[0]), "=r"(r[1]), "=r"(r[2]), "=r"(r[3]) : "r"(addr));
}
DI void barx(int id, int n) {
    asm volatile("bar.sync %0, %1;" :: "r"(id), "r"(n) : "memory");
}
// m16n8k16 fp16 MMA, f32 accumulate (baseline PTX, sm_80+)
DI void mma16(float* d, const uint32_t* a, const uint32_t* b) {
    asm volatile(
        "mma.sync.aligned.m16n8k16.row.col.f32.f16.f16.f32 "
        "{%0,%1,%2,%3}, {%4,%5,%6,%7}, {%8,%9}, {%0,%1,%2,%3};"
        : "+f"(d[0]), "+f"(d[1]), "+f"(d[2]), "+f"(d[3])
        : "r"(a[0]), "r"(a[1]), "r"(a[2]), "r"(a[3]), "r"(b[0]), "r"(b[1]));
}

// ---------------------------------------------------------------------------
// Kernel 1: codebook normalize -> fp16 hi/mid fragment-packed g_cf.
//   Block (nt, kt16): lane ln (g=ln>>2, tid=ln&3):
//     b0 = (k=kt*16+tid*2 (+1), n=nt*8+g), b1 = k+8. uint4 {b0h,b1h,b0m,b1m}.
// ---------------------------------------------------------------------------
__global__ __launch_bounds__(256) void norm_cb_fp(const float* __restrict__ cb) {
    __shared__ float sc[16][516];
    int t = threadIdx.x, lane = t & 31, w = t >> 5;
    int R0 = blockIdx.x * 16;
#pragma unroll
    for (int rr = 0; rr < 2; rr++) {
        int row = 2 * w + rr;
        const float4* rp = (const float4*)(cb + (size_t)(R0 + row) * D_DIM);
        float4 v[4]; float ss = 0.f;
#pragma unroll
        for (int i = 0; i < 4; i++) {
            v[i] = rp[lane + 32 * i];
            ss += v[i].x * v[i].x + v[i].y * v[i].y + v[i].z * v[i].z + v[i].w * v[i].w;
        }
#pragma unroll
        for (int o = 16; o; o >>= 1) ss += __shfl_xor_sync(0xffffffffu, ss, o);
        float inv = 1.0f / fmaxf(sqrtf(ss), 1e-8f);
#pragma unroll
        for (int i = 0; i < 4; i++) {
            float4 q; q.x = v[i].x * inv; q.y = v[i].y * inv;
            q.z = v[i].z * inv; q.w = v[i].w * inv;
            *(float4*)&sc[row][4 * (lane + 32 * i)] = q;
        }
    }
    __syncthreads();
    uint32_t* outp = g_cf + (size_t)blockIdx.x * 8192;   // 2 nt x 32 kt x 32 ln x uint4
#pragma unroll
    for (int q = 0; q < 8; q++) {
        int p = t + q * 256;                 // 0..2047
        int nt_l = p >> 10, pp = p & 1023;
        int kt = pp >> 5, ln = pp & 31;
        int g = ln >> 2, tid = ln & 3;
        int nl = nt_l * 8 + g;
        int k0 = kt * 16 + tid * 2;
        uint32_t b0h, b0m, b1h, b1m;
        f16_split2(sc[nl][k0],     sc[nl][k0 + 1], b0h, b0m);
        f16_split2(sc[nl][k0 + 8], sc[nl][k0 + 9], b1h, b1m);
        uint4 o; o.x = b0h; o.y = b1h; o.z = b0m; o.w = b1m;
        *(uint4*)(outp + (size_t)((nt_l * 32 + kt) * 32 + ln) * 4) = o;
    }
}

// ---------------------------------------------------------------------------
// Kernel 2: x = 0.5*st/||st|| + 0.5*ad/||ad||, fp16 hi/mid packed g_xf.
//   Block (mt, kt16): [hi: lane*16B {a0h..a3h}] [mid: +512B {a0m..a3m}]
//   a0:(m=mt*16+g, k=kt*16+tid*2,+1)  a1:m+8  a2:k+8  a3:m+8,k+8
// ---------------------------------------------------------------------------
__global__ __launch_bounds__(256) void combine_fp(const float* __restrict__ st,
                                                  const float* __restrict__ ad) {
    __shared__ float sx[16][516];
    int t = threadIdx.x, lane = t & 31, w = t >> 5;
    int R0 = blockIdx.x * 16;
#pragma unroll
    for (int rr = 0; rr < 2; rr++) {
        int row = 2 * w + rr;
        const float4* sp = (const float4*)(st + (size_t)(R0 + row) * D_DIM);
        const float4* ap = (const float4*)(ad + (size_t)(R0 + row) * D_DIM);
        float4 sv[4], av[4]; float ss = 0.f, aa = 0.f;
#pragma unroll
        for (int i = 0; i < 4; i++) {
            sv[i] = sp[lane + 32 * i];
            av[i] = ap[lane + 32 * i];
            ss += sv[i].x*sv[i].x + sv[i].y*sv[i].y + sv[i].z*sv[i].z + sv[i].w*sv[i].w;
            aa += av[i].x*av[i].x + av[i].y*av[i].y + av[i].z*av[i].z + av[i].w*av[i].w;
        }
#pragma unroll
        for (int o = 16; o; o >>= 1) {
            ss += __shfl_xor_sync(0xffffffffu, ss, o);
            aa += __shfl_xor_sync(0xffffffffu, aa, o);
        }
        float is = 0.5f / fmaxf(sqrtf(ss), 1e-8f);
        float ia = 0.5f / fmaxf(sqrtf(aa), 1e-8f);
#pragma unroll
        for (int i = 0; i < 4; i++) {
            float4 q;
            q.x = sv[i].x * is + av[i].x * ia;
            q.y = sv[i].y * is + av[i].y * ia;
            q.z = sv[i].z * is + av[i].z * ia;
            q.w = sv[i].w * is + av[i].w * ia;
            *(float4*)&sx[row][4 * (lane + 32 * i)] = q;
        }
    }
    __syncthreads();
    uint32_t* outp = g_xf + (size_t)blockIdx.x * 8192;   // 32 kt x 256 uint32
#pragma unroll
    for (int q = 0; q < 4; q++) {
        int p = t + q * 256;                 // 0..1023 = (kt, ln)
        int kt = p >> 5, ln = p & 31;
        int g = ln >> 2, tid = ln & 3;
        int k0 = kt * 16 + tid * 2;
        uint32_t h0, m0, h1, m1, h2, m2, h3, m3;
        f16_split2(sx[g][k0],         sx[g][k0 + 1],     h0, m0);
        f16_split2(sx[g + 8][k0],     sx[g + 8][k0 + 1], h1, m1);
        f16_split2(sx[g][k0 + 8],     sx[g][k0 + 9],     h2, m2);
        f16_split2(sx[g + 8][k0 + 8], sx[g + 8][k0 + 9], h3, m3);
        uint4 H; H.x = h0; H.y = h1; H.z = h2; H.w = h3;
        uint4 M; M.x = m0; M.y = m1; M.z = m2; M.w = m3;
        uint32_t base = kt * 256;
        *(uint4*)(outp + base + ln * 4)       = H;
        *(uint4*)(outp + base + 128 + ln * 4) = M;
    }
}

// ---------------------------------------------------------------------------
// Kernel 3: 3xFP16 m16n8k16 GEMM, 256(M) x 128(N) tile, BK=32, 16 chunks,
//   double-buffered cp.async. 320 threads: 8 HMMA warps (wm 0..3 x wn 0..1,
//   64x64 each) + 2 noise warps (nz for rows m-subtile 0,1 of each warp).
// SMEM: A 2x32KB [0,65536); B 2x16KB [65536,98304); nz float2[16384] @98304;
//       rm/ri/rs reuse [0,3072) post-mainloop. Total 229376 B.
// ---------------------------------------------------------------------------
#define NZ_OFF 98304
#define SMEMB  229376

DI void issue_chunk(int c, int s, uint32_t sbase, int mtb, int ntb, int t) {
    int kt0 = c * 2;
#pragma unroll
    for (int i = 0; i < 8; i++) {          // A: 2048 x 16B
        int u = t + i * 256;
        int bi = u >> 6, off = u & 63;     // bi = mt*2+ktl
        const uint32_t* g = g_xf
            + ((size_t)(mtb + (bi >> 1)) * 32 + kt0 + (bi & 1)) * 256 + off * 4;
        cp16(sbase + (uint32_t)(s * 32768 + bi * 1024 + off * 16), g);
    }
#pragma unroll
    for (int i = 0; i < 4; i++) {          // B: 1024 x 16B
        int u = t + i * 256;
        int bi = u >> 5, off = u & 31;     // bi = nt*2+ktl
        const uint32_t* g = g_cf
            + ((size_t)(ntb + (bi >> 1)) * 32 + kt0 + (bi & 1)) * 128 + off * 4;
        cp16(sbase + (uint32_t)(65536 + s * 16384 + bi * 512 + off * 16), g);
    }
}

__global__ __launch_bounds__(320, 1) void gemm_mma(
        float* __restrict__ ws,
        uint32_t k1a, uint32_t k1b, uint32_t k2a, uint32_t k2b) {
    extern __shared__ char smem[];
    const uint32_t sbase = smem_u32(smem);
    float2* nz = (float2*)(smem + NZ_OFF);
    const int t = threadIdx.x, lane = t & 31;
    const int mtb = blockIdx.y * 16, ntb = blockIdx.x * 16;
    const int bm = blockIdx.y * 256, bn = blockIdx.x * 128;

    if (t < 256) {
        // ================= HMMA GEMM role =================
        const int wid = t >> 5;
        const int wm = wid >> 1, wn = wid & 1;
        const int g = lane >> 2;

        float acc[32][4];
#pragma unroll
        for (int i = 0; i < 32; i++)
#pragma unroll
            for (int j = 0; j < 4; j++) acc[i][j] = 0.f;

        issue_chunk(0, 0, sbase, mtb, ntb, t);
        CP_COMMIT();
        issue_chunk(1, 1, sbase, mtb, ntb, t);
        CP_COMMIT();

        for (int c = 0; c < 16; c++) {
            if (c < 15) { CP_WAIT1(); } else { CP_WAIT0(); }
            barx(1, 256);
            const uint32_t AS = sbase + (uint32_t)((c & 1) * 32768);
            const uint32_t BS = sbase + (uint32_t)(65536 + (c & 1) * 16384);
#pragma unroll
            for (int ktl = 0; ktl < 2; ktl++) {
                uint32_t ah[4][4], am[4][4];
#pragma unroll
                for (int m = 0; m < 4; m++) {
                    uint32_t base = AS + (uint32_t)(((wm * 4 + m) * 2 + ktl) * 1024 + lane * 16);
                    lds128(ah[m], base);
                    lds128(am[m], base + 512);
                }
#pragma unroll
                for (int g2 = 0; g2 < 2; g2++) {
#pragma unroll
                    for (int n4 = 0; n4 < 4; n4++) {
                        uint32_t bv[4];
                        lds128(bv, BS + (uint32_t)((((wn * 8 + g2 * 4 + n4) * 2 + ktl) * 512) + lane * 16));
                        uint32_t bh[2], bmid[2];
                        bh[0] = bv[0]; bh[1] = bv[1];
                        bmid[0] = bv[2]; bmid[1] = bv[3];
#pragma unroll
                        for (int m = 0; m < 4; m++) {
                            float* A = acc[m * 8 + g2 * 4 + n4];
                            mma16(A, ah[m], bh);
                            mma16(A, ah[m], bmid);
                            mma16(A, am[m], bh);
                        }
                    }
                }
            }
            barx(1, 256);
            if (c + 2 < 16) {
                issue_chunk(c + 2, c & 1, sbase, mtb, ntb, t);
                CP_COMMIT();
            }
        }

        __syncthreads();   // join #1 with noise warps

        // ---- epilogue: m<2 rows use precomputed nz; m>=2 inline threefry ----
        float rmax[8], rsum[8]; int ridx[8];
#pragma unroll
        for (int m = 0; m < 4; m++)
#pragma unroll
        for (int h = 0; h < 2; h++) {
            int e = m * 2 + h;
            int rowloc = wm * 64 + m * 16 + h * 8 + g;
            int colb = wn * 64 + (lane & 3) * 2;
            int grow = bm + rowloc;
            float bmax = -3.4e38f; int bidx = 0; float bsum = 0.f;
            float* wrow = ws + (size_t)grow * 1024 + bn;
            if (m < 2) {
                int nzbase = (wm * 32 + m * 16 + h * 8 + g) * 128;
#pragma unroll
                for (int n = 0; n < 8; n++) {
                    int ccl = colb + n * 8;
                    float s0 = acc[m * 8 + n][h * 2];
                    float s1 = acc[m * 8 + n][h * 2 + 1];
                    float4 nv = *(float4*)&nz[nzbase + ccl];
                    float v1a = s0 + nv.x;
                    if (v1a > bmax) { bmax = v1a; bidx = bn + ccl; }
                    float v1b = s1 + nv.z;
                    if (v1b > bmax) { bmax = v1b; bidx = bn + ccl + 1; }
                    float p0 = __expf(s0) * nv.y;
                    float p1 = __expf(s1) * nv.w;
                    bsum += p0 + p1;
                    *(float2*)(wrow + ccl) = make_float2(p0, p1);
                }
            } else {
                uint32_t ctrb = (uint32_t)grow * 1024u + (uint32_t)bn;
#pragma unroll
                for (int n = 0; n < 8; n++) {
                    int ccl = colb + n * 8;
                    float s0 = acc[m * 8 + n][h * 2];
                    float s1 = acc[m * 8 + n][h * 2 + 1];
                    uint32_t i0 = ctrb + (uint32_t)ccl;
                    float v1a = s0 + gumbel_from_bits(tf_bits(k1a, k1b, i0));
                    if (v1a > bmax) { bmax = v1a; bidx = bn + ccl; }
                    float v1b = s1 + gumbel_from_bits(tf_bits(k1a, k1b, i0 + 1u));
                    if (v1b > bmax) { bmax = v1b; bidx = bn + ccl + 1; }
                    float p0 = __expf(s0) * expg_from_bits(tf_bits(k2a, k2b, i0));
                    float p1 = __expf(s1) * expg_from_bits(tf_bits(k2a, k2b, i0 + 1u));
                    bsum += p0 + p1;
                    *(float2*)(wrow + ccl) = make_float2(p0, p1);
                }
            }
#pragma unroll
            for (int o = 1; o <= 2; o <<= 1) {
                float om = __shfl_xor_sync(0xffffffffu, bmax, o);
                int   oi = __shfl_xor_sync(0xffffffffu, bidx, o);
                float os = __shfl_xor_sync(0xffffffffu, bsum, o);
                if (om > bmax || (om == bmax && oi < bidx)) { bmax = om; bidx = oi; }
                bsum += os;
            }
            rmax[e] = bmax; ridx[e] = bidx; rsum[e] = bsum;
        }

        float* rm = (float*)(smem);
        int*   ri = (int*)  (smem + 1024);
        float* rs = (float*)(smem + 2048);
        if (wn == 1 && (lane & 3) == 0) {
#pragma unroll
            for (int e = 0; e < 8; e++) {
                int rl = wm * 64 + (e >> 1) * 16 + (e & 1) * 8 + g;
                rm[rl] = rmax[e]; ri[rl] = ridx[e]; rs[rl] = rsum[e];
            }
        }
        __syncthreads();   // join #2
        if (wn == 0 && (lane & 3) == 0) {
#pragma unroll
            for (int e = 0; e < 8; e++) {
                int rl = wm * 64 + (e >> 1) * 16 + (e & 1) * 8 + g;
                float om = rm[rl]; int oi = ri[rl]; float os = rs[rl];
                float bmv = rmax[e]; int biv = ridx[e];
                if (om > bmv || (om == bmv && oi < biv)) { bmv = om; biv = oi; }
                size_t pidx = (size_t)(bm + rl) * NBN + blockIdx.x;
                g_pm[pidx] = bmv; g_pi[pidx] = biv; g_ps[pidx] = rsum[e] + os;
            }
        }
    } else {
        // ================= noise role: rows (wm*64 + 0..31) x 128 cols =====
        const int jj = t - 256;   // 0..63
#pragma unroll 1
        for (int it = 0; it < 256; it++) {
            int idx = it * 64 + jj;            // 0..16383
            int nzr = idx >> 7, col = idx & 127;
            int wmn = nzr >> 5, wi = nzr & 31;
            int grow = bm + wmn * 64 + wi;
            uint32_t ctr = (uint32_t)grow * 1024u + (uint32_t)(bn + col);
            uint32_t b1 = tf_bits(k1a, k1b, ctr);
            float u1 = __uint_as_float((b1 >> 9) | 0x3f800000u) - 1.0f;
            float m1 = -__nv_logf(fmaxf(TINYF, u1 + TINYF));
            float g1 = -__nv_logf(m1);
            uint32_t b2 = tf_bits(k2a, k2b, ctr);
            float u2 = __uint_as_float((b2 >> 9) | 0x3f800000u) - 1.0f;
            float eg = -__fdividef(1.0f, __nv_logf(fmaxf(TINYF, u2 + TINYF)));
            nz[idx] = make_float2(g1, eg);
        }
        __syncthreads();   // join #1
        __syncthreads();   // join #2
    }
}

// ---------------------------------------------------------------------------
// Kernel 4: reduce partials per row, normalize ws, gather z_q, indices.
// ---------------------------------------------------------------------------
__global__ void finalize_kernel(const float* __restrict__ cb,
                                float* __restrict__ zq,
                                float* __restrict__ ws,
                                float* __restrict__ idxo) {
    int n = blockIdx.x, t = threadIdx.x;
    __shared__ int   s_best;
    __shared__ float s_inv;
    if (t == 0) {
        float bm = g_pm[(size_t)n * NBN]; int bi = g_pi[(size_t)n * NBN];
        float sum = g_ps[(size_t)n * NBN];
#pragma unroll
        for (int j = 1; j < NBN; j++) {
            float m = g_pm[(size_t)n * NBN + j];
            int   i = g_pi[(size_t)n * NBN + j];
            if (m > bm || (m == bm && i < bi)) { bm = m; bi = i; }
            sum += g_ps[(size_t)n * NBN + j];
        }
        s_best = bi;
        s_inv  = 1.0f / sum;
    }
    __syncthreads();
    int best = s_best; float inv = s_inv;

    float4* wrow = (float4*)(ws + (size_t)n * 1024);
    float4 v = wrow[t];
    v.x *= inv; v.y *= inv; v.z *= inv; v.w *= inv;
    wrow[t] = v;

    if (t < 128) {
        float4 c = *(const float4*)(cb + (size_t)best * D_DIM + t * 4);
        *(float4*)(zq + (size_t)n * D_DIM + t * 4) = c;
    }
    if (t == 0) idxo[n] = (float)best;
}

// ---------------------------------------------------------------------------
extern "C" void kernel_launch(void* const* d_in, const int* in_sizes, int n_in,
                              void* d_out, int out_size) {
    const float* st = (const float*)d_in[0];
    const float* ad = (const float*)d_in[1];
    const float* cb = (const float*)d_in[2];
    int N = in_sizes[0] / D_DIM;     // 32768
    int K = in_sizes[2] / D_DIM;     // 1024

    float* out  = (float*)d_out;
    float* zq   = out;                              // [N, D]
    float* ws   = out + (size_t)N * D_DIM;          // [N, K]
    float* idxo = ws + (size_t)N * K;               // [N, 1]

    // jax.random.key(42) -> (0,42); partitionable fold split
    uint32_t g1a = 0u, g1b = 0u;
    threefry2x32(0u, 42u, g1a, g1b);    // counter 0 -> gk1
    uint32_t g2a = 0u, g2b = 1u;
    threefry2x32(0u, 42u, g2a, g2b);    // counter 1 -> gk2

    cudaFuncSetAttribute(gemm_mma,
        cudaFuncAttributeMaxDynamicSharedMemorySize, SMEMB);

    norm_cb_fp<<<K / 16, 256>>>(cb);
    combine_fp<<<N / 16, 256>>>(st, ad);
    dim3 gg(K / 128, N / 256);          // (8, 128)
    gemm_mma<<<gg, 320, SMEMB>>>(ws, g1a, g1b, g2a, g2b);
    finalize_kernel<<<N, 256>>>(cb, zq, ws, idxo);
}

// round 13
// speedup vs baseline: 1.2980x; 1.2980x over previous
#include <cuda_runtime.h>
#include <cstdint>
#include <cstddef>

#define DI __device__ __forceinline__
static const int D_DIM = 512;
#define MAXN 32768
#define MAXK 1024
#define NBN  8
#define TAU  2e-3f

extern "C" __device__ float __nv_logf(float);

// Scratch (device globals; no allocation allowed)
__device__ uint32_t g_xf[(size_t)2048 * 64 * 128]; // 64MB: A tf32-hi blocks (mt16,kt8): lane->uint4
__device__ uint32_t g_cf[(size_t)128 * 64 * 64];   //  2MB: B tf32-hi blocks (nt8,kt8): lane->uint2
__device__ float g_x [(size_t)MAXN * D_DIM];       // 64MB fp32 combined input (repair)
__device__ float g_cn[(size_t)MAXK * D_DIM];       //  2MB fp32 normalized codebook (repair)
__device__ float g_pm[(size_t)MAXN * NBN];
__device__ int   g_pi[(size_t)MAXN * NBN];
__device__ float g_ps[(size_t)MAXN * NBN];
__device__ float g_p2[(size_t)MAXN * NBN];         // per-tile second max

// ---------------------------------------------------------------------------
// Threefry-2x32 (exact JAX, partitionable mode)
// ---------------------------------------------------------------------------
__host__ __device__ inline uint32_t rotl32(uint32_t x, int r) {
    return (x << r) | (x >> (32 - r));
}
__host__ __device__ inline void threefry2x32(uint32_t k0, uint32_t k1,
                                             uint32_t& x0, uint32_t& x1) {
    uint32_t k2 = k0 ^ k1 ^ 0x1BD11BDAu;
    x0 += k0; x1 += k1;
#define TFR(r) { x0 += x1; x1 = rotl32(x1, r); x1 ^= x0; }
    TFR(13) TFR(15) TFR(26) TFR(6)
    x0 += k1; x1 += k2 + 1u;
    TFR(17) TFR(29) TFR(16) TFR(24)
    x0 += k2; x1 += k0 + 2u;
    TFR(13) TFR(15) TFR(26) TFR(6)
    x0 += k0; x1 += k1 + 3u;
    TFR(17) TFR(29) TFR(16) TFR(24)
    x0 += k1; x1 += k2 + 4u;
    TFR(13) TFR(15) TFR(26) TFR(6)
    x0 += k2; x1 += k0 + 5u;
#undef TFR
}
DI uint32_t tf_bits(uint32_t k0, uint32_t k1, uint32_t i) {
    uint32_t x0 = 0u, x1 = i;
    threefry2x32(k0, k1, x0, x1);
    return x0 ^ x1;
}
#define TINYF 1.17549435e-38f
DI float gumbel_from_bits(uint32_t bits) {
    float u = __uint_as_float((bits >> 9) | 0x3f800000u) - 1.0f;
    float r = fmaxf(TINYF, u + TINYF);
    return -__nv_logf(-__nv_logf(r));
}

// ---------------------------------------------------------------------------
// low-level helpers
// ---------------------------------------------------------------------------
DI uint32_t smem_u32(const void* p) {
    uint32_t a;
    asm("{ .reg .u64 t; cvta.to.shared.u64 t, %1; cvt.u32.u64 %0, t; }"
        : "=r"(a) : "l"(p));
    return a;
}
DI uint32_t tf32h(float x) {
    uint32_t h; asm("cvt.rna.tf32.f32 %0, %1;" : "=r"(h) : "f"(x)); return h;
}
DI void cp16(uint32_t saddr, const void* g) {
    asm volatile("cp.async.cg.shared.global [%0], [%1], 16;"
                 :: "r"(saddr), "l"(g) : "memory");
}
#define CP_COMMIT() asm volatile("cp.async.commit_group;" ::: "memory")
#define CP_WAIT1()  asm volatile("cp.async.wait_group 1;" ::: "memory")
#define CP_WAIT0()  asm volatile("cp.async.wait_group 0;" ::: "memory")
DI void lds128(uint32_t* r, uint32_t addr) {
    asm volatile("ld.shared.v4.b32 {%0,%1,%2,%3}, [%4];"
        : "=r"(r[0]), "=r"(r[1]), "=r"(r[2]), "=r"(r[3]) : "r"(addr));
}
DI void lds64(uint32_t* r, uint32_t addr) {
    asm volatile("ld.shared.v2.b32 {%0,%1}, [%2];"
        : "=r"(r[0]), "=r"(r[1]) : "r"(addr));
}
DI void barx(int id, int n) {
    asm volatile("bar.sync %0, %1;" :: "r"(id), "r"(n) : "memory");
}
// m16n8k8 tf32 MMA (baseline PTX, drives tensor pipe on sm_103)
DI void mma8(float* d, const uint32_t* a, const uint32_t* b) {
    asm volatile(
        "mma.sync.aligned.m16n8k8.row.col.f32.tf32.tf32.f32 "
        "{%0,%1,%2,%3}, {%4,%5,%6,%7}, {%8,%9}, {%0,%1,%2,%3};"
        : "+f"(d[0]), "+f"(d[1]), "+f"(d[2]), "+f"(d[3])
        : "r"(a[0]), "r"(a[1]), "r"(a[2]), "r"(a[3]), "r"(b[0]), "r"(b[1]));
}

// ---------------------------------------------------------------------------
// Kernel 1: codebook normalize -> g_cn fp32 + tf32-hi fragment-packed g_cf.
//   B frag (m16n8k8, .row.col): lane ln (g=ln>>2, tid=ln&3):
//     b0 = (k = kt*8+tid, n = nt*8+g), b1 = k+4. uint2 {b0h, b1h}.
// ---------------------------------------------------------------------------
__global__ __launch_bounds__(256) void norm_cb_fp(const float* __restrict__ cb) {
    __shared__ float sc[16][516];
    int t = threadIdx.x, lane = t & 31, w = t >> 5;
    int R0 = blockIdx.x * 16;
#pragma unroll
    for (int rr = 0; rr < 2; rr++) {
        int row = 2 * w + rr;
        const float4* rp = (const float4*)(cb + (size_t)(R0 + row) * D_DIM);
        float4 v[4]; float ss = 0.f;
#pragma unroll
        for (int i = 0; i < 4; i++) {
            v[i] = rp[lane + 32 * i];
            ss += v[i].x * v[i].x + v[i].y * v[i].y + v[i].z * v[i].z + v[i].w * v[i].w;
        }
#pragma unroll
        for (int o = 16; o; o >>= 1) ss += __shfl_xor_sync(0xffffffffu, ss, o);
        float inv = 1.0f / fmaxf(sqrtf(ss), 1e-8f);
        float4* cn = (float4*)(g_cn + (size_t)(R0 + row) * D_DIM);
#pragma unroll
        for (int i = 0; i < 4; i++) {
            float4 q; q.x = v[i].x * inv; q.y = v[i].y * inv;
            q.z = v[i].z * inv; q.w = v[i].w * inv;
            cn[lane + 32 * i] = q;
            *(float4*)&sc[row][4 * (lane + 32 * i)] = q;
        }
    }
    __syncthreads();
    uint32_t* outp = g_cf + (size_t)blockIdx.x * 8192;   // 2 nt x 64 kt x 64 u32
#pragma unroll
    for (int q = 0; q < 16; q++) {
        int p = t * 16 + q;                 // 0..4095
        int nt_l = p >> 11, pp = p & 2047;
        int kt = pp >> 5, ln = pp & 31;
        int nl = nt_l * 8 + (ln >> 2);
        int c  = kt * 8 + (ln & 3);
        uint32_t b0 = tf32h(sc[nl][c]);
        uint32_t b1 = tf32h(sc[nl][c + 4]);
        uint2 o; o.x = b0; o.y = b1;
        *(uint2*)(outp + (size_t)((nt_l * 64 + kt) * 64 + ln * 2)) = o;
    }
}

// ---------------------------------------------------------------------------
// Kernel 2: x = 0.5*st/||st|| + 0.5*ad/||ad|| -> g_x fp32 + tf32-hi g_xf.
//   A frag: lane ln (g=ln>>2, tid=ln&3): a0=(m=mt*16+g, k=kt*8+tid),
//   a1=(m+8,k), a2=(m,k+4), a3=(m+8,k+4). uint4 per lane.
// ---------------------------------------------------------------------------
__global__ __launch_bounds__(256) void combine_fp(const float* __restrict__ st,
                                                  const float* __restrict__ ad) {
    __shared__ float sx[16][516];
    int t = threadIdx.x, lane = t & 31, w = t >> 5;
    int R0 = blockIdx.x * 16;
#pragma unroll
    for (int rr = 0; rr < 2; rr++) {
        int row = 2 * w + rr;
        const float4* sp = (const float4*)(st + (size_t)(R0 + row) * D_DIM);
        const float4* ap = (const float4*)(ad + (size_t)(R0 + row) * D_DIM);
        float4 sv[4], av[4]; float ss = 0.f, aa = 0.f;
#pragma unroll
        for (int i = 0; i < 4; i++) {
            sv[i] = sp[lane + 32 * i];
            av[i] = ap[lane + 32 * i];
            ss += sv[i].x*sv[i].x + sv[i].y*sv[i].y + sv[i].z*sv[i].z + sv[i].w*sv[i].w;
            aa += av[i].x*av[i].x + av[i].y*av[i].y + av[i].z*av[i].z + av[i].w*av[i].w;
        }
#pragma unroll
        for (int o = 16; o; o >>= 1) {
            ss += __shfl_xor_sync(0xffffffffu, ss, o);
            aa += __shfl_xor_sync(0xffffffffu, aa, o);
        }
        float is = 0.5f / fmaxf(sqrtf(ss), 1e-8f);
        float ia = 0.5f / fmaxf(sqrtf(aa), 1e-8f);
        float4* xr = (float4*)(g_x + (size_t)(R0 + row) * D_DIM);
#pragma unroll
        for (int i = 0; i < 4; i++) {
            float4 q;
            q.x = sv[i].x * is + av[i].x * ia;
            q.y = sv[i].y * is + av[i].y * ia;
            q.z = sv[i].z * is + av[i].z * ia;
            q.w = sv[i].w * is + av[i].w * ia;
            xr[lane + 32 * i] = q;
            *(float4*)&sx[row][4 * (lane + 32 * i)] = q;
        }
    }
    __syncthreads();
    uint32_t* outp = g_xf + (size_t)blockIdx.x * 8192;   // 64 kt x 32 ln x uint4
#pragma unroll
    for (int q = 0; q < 8; q++) {
        int p = t * 8 + q;                  // 0..2047 = (kt, ln)
        int kt = p >> 5, ln = p & 31;
        int g = ln >> 2, c = kt * 8 + (ln & 3);
        uint4 H;
        H.x = tf32h(sx[g][c]);
        H.y = tf32h(sx[g + 8][c]);
        H.z = tf32h(sx[g][c + 4]);
        H.w = tf32h(sx[g + 8][c + 4]);
        *(uint4*)(outp + (size_t)p * 4) = H;
    }
}

// ---------------------------------------------------------------------------
// Kernel 3: 1xTF32 GEMM (128x128, BK=32, double-buffered) + 4 noise warps.
//   Epilogue tracks TOP-2 of (sim+g1) per row tile for the repair pass.
// SMEM: A 2x16KB [0,32768); B 2x16KB [32768,65536); nz float2[16384] @65536.
//       post-mainloop: rm@0, ri@1024, rs@2048, rm2@3072 (reuse A region).
// ---------------------------------------------------------------------------
#define NZ_OFF 65536
#define SMEMB  196608

DI void issue_chunk(int c, int s, uint32_t sbase, int mtb, int ntb, int t) {
    int kt0 = c * 4;
#pragma unroll
    for (int i = 0; i < 4; i++) {          // A: 1024 x 16B
        int u = t + i * 256;
        int blk = u >> 5, off = u & 31;    // blk = mt_l*4 + ktl
        const uint32_t* g = g_xf
            + ((size_t)(mtb + (blk >> 2)) * 64 + kt0 + (blk & 3)) * 128 + off * 4;
        cp16(sbase + (uint32_t)(s * 16384 + blk * 512 + off * 16), g);
    }
#pragma unroll
    for (int i = 0; i < 4; i++) {          // B: 1024 x 16B
        int u = t + i * 256;
        int blk = u >> 4, off = u & 15;    // blk = nt_l*4 + ktl; off = lane pair
        const uint32_t* g = g_cf
            + ((size_t)(ntb + (blk >> 2)) * 64 + kt0 + (blk & 3)) * 64 + off * 4;
        cp16(sbase + (uint32_t)(32768 + s * 16384 + blk * 256 + off * 16), g);
    }
}

__global__ __launch_bounds__(384, 1) void gemm_mma(
        float* __restrict__ ws,
        uint32_t k1a, uint32_t k1b, uint32_t k2a, uint32_t k2b) {
    extern __shared__ char smem[];
    const uint32_t sbase = smem_u32(smem);
    float2* nz = (float2*)(smem + NZ_OFF);
    const int t = threadIdx.x, lane = t & 31;
    const int mtb = blockIdx.y * 8, ntb = blockIdx.x * 16;
    const int bm = blockIdx.y * 128, bn = blockIdx.x * 128;

    if (t < 256) {
        // ================= HMMA GEMM role =================
        const int wid = t >> 5;
        const int wm = wid >> 1, wn = wid & 1;
        const int g = lane >> 2;

        float acc[16][4];
#pragma unroll
        for (int i = 0; i < 16; i++)
#pragma unroll
            for (int j = 0; j < 4; j++) acc[i][j] = 0.f;

        issue_chunk(0, 0, sbase, mtb, ntb, t);
        CP_COMMIT();
        issue_chunk(1, 1, sbase, mtb, ntb, t);
        CP_COMMIT();

        for (int c = 0; c < 16; c++) {
            if (c < 15) { CP_WAIT1(); } else { CP_WAIT0(); }
            barx(1, 256);
            const uint32_t AS = sbase + (uint32_t)((c & 1) * 16384);
            const uint32_t BS = sbase + (uint32_t)(32768 + (c & 1) * 16384);
#pragma unroll
            for (int ktl = 0; ktl < 4; ktl++) {
                uint32_t ah[2][4];
#pragma unroll
                for (int m = 0; m < 2; m++)
                    lds128(ah[m], AS + (uint32_t)(((wm * 2 + m) * 4 + ktl) * 512 + lane * 16));
#pragma unroll
                for (int g2 = 0; g2 < 2; g2++) {
#pragma unroll
                    for (int n4 = 0; n4 < 4; n4++) {
                        uint32_t bh[2];
                        lds64(bh, BS + (uint32_t)(((wn * 8 + g2 * 4 + n4) * 4 + ktl) * 256 + lane * 8));
#pragma unroll
                        for (int m = 0; m < 2; m++)
                            mma8(acc[m * 8 + g2 * 4 + n4], ah[m], bh);
                    }
                }
            }
            barx(1, 256);
            if (c + 2 < 16) {
                issue_chunk(c + 2, c & 1, sbase, mtb, ntb, t);
                CP_COMMIT();
            }
        }

        __syncthreads();   // join #1 with noise warps

        // ---- epilogue: top-2 argmax partials + exp-path into ws ----
        float rmax[4], rmax2[4], rsum[4]; int ridx[4];
#pragma unroll
        for (int m = 0; m < 2; m++)
#pragma unroll
        for (int h = 0; h < 2; h++) {
            int e = m * 2 + h;
            int rowloc = wm * 32 + m * 16 + h * 8 + g;
            int colb = wn * 64 + (lane & 3) * 2;
            int grow = bm + rowloc;
            float bmax = -3.4e38f, bmax2 = -3.4e38f; int bidx = 0; float bsum = 0.f;
            float* wrow = ws + (size_t)grow * 1024 + bn;
#pragma unroll
            for (int n = 0; n < 8; n++) {
                int ccl = colb + n * 8;
                float s0 = acc[m * 8 + n][h * 2];
                float s1 = acc[m * 8 + n][h * 2 + 1];
                float4 nv = *(float4*)&nz[rowloc * 128 + ccl];
                float v1a = s0 + nv.x;
                if (v1a > bmax) { bmax2 = bmax; bmax = v1a; bidx = bn + ccl; }
                else if (v1a > bmax2) bmax2 = v1a;
                float v1b = s1 + nv.z;
                if (v1b > bmax) { bmax2 = bmax; bmax = v1b; bidx = bn + ccl + 1; }
                else if (v1b > bmax2) bmax2 = v1b;
                float p0 = __expf(s0) * nv.y;
                float p1 = __expf(s1) * nv.w;
                bsum += p0 + p1;
                *(float2*)(wrow + ccl) = make_float2(p0, p1);
            }
#pragma unroll
            for (int o = 1; o <= 2; o <<= 1) {
                float om  = __shfl_xor_sync(0xffffffffu, bmax, o);
                int   oi  = __shfl_xor_sync(0xffffffffu, bidx, o);
                float om2 = __shfl_xor_sync(0xffffffffu, bmax2, o);
                float os  = __shfl_xor_sync(0xffffffffu, bsum, o);
                float hi2 = fmaxf(fminf(bmax, om), fmaxf(bmax2, om2));
                if (om > bmax || (om == bmax && oi < bidx)) { bmax = om; bidx = oi; }
                bmax2 = hi2;
                bsum += os;
            }
            rmax[e] = bmax; rmax2[e] = bmax2; ridx[e] = bidx; rsum[e] = bsum;
        }

        float* rm  = (float*)(smem);
        int*   ri  = (int*)  (smem + 1024);
        float* rs  = (float*)(smem + 2048);
        float* rm2 = (float*)(smem + 3072);
        if (wn == 1 && (lane & 3) == 0) {
#pragma unroll
            for (int e = 0; e < 4; e++) {
                int rl = wm * 32 + (e >> 1) * 16 + (e & 1) * 8 + g;
                rm[rl] = rmax[e]; ri[rl] = ridx[e]; rs[rl] = rsum[e]; rm2[rl] = rmax2[e];
            }
        }
        __syncthreads();   // join #2
        if (wn == 0 && (lane & 3) == 0) {
#pragma unroll
            for (int e = 0; e < 4; e++) {
                int rl = wm * 32 + (e >> 1) * 16 + (e & 1) * 8 + g;
                float om = rm[rl]; int oi = ri[rl]; float os = rs[rl]; float om2 = rm2[rl];
                float bmv = rmax[e]; int biv = ridx[e];
                float hi2 = fmaxf(fminf(bmv, om), fmaxf(rmax2[e], om2));
                if (om > bmv || (om == bmv && oi < biv)) { bmv = om; biv = oi; }
                size_t pidx = (size_t)(bm + rl) * NBN + blockIdx.x;
                g_pm[pidx] = bmv; g_pi[pidx] = biv;
                g_ps[pidx] = rsum[e] + os; g_p2[pidx] = hi2;
            }
        }
    } else {
        // ================= noise role: 16384 elems =================
        const int jj = t - 256;   // 0..127
#pragma unroll 1
        for (int it = 0; it < 128; it++) {
            int idx = it * 128 + jj;
            int row = idx >> 7, col = idx & 127;
            uint32_t ctr = (uint32_t)(bm + row) * 1024u + (uint32_t)(bn + col);
            uint32_t b1 = tf_bits(k1a, k1b, ctr);
            float u1 = __uint_as_float((b1 >> 9) | 0x3f800000u) - 1.0f;
            float m1 = -__nv_logf(fmaxf(TINYF, u1 + TINYF));
            float g1 = -__nv_logf(m1);
            uint32_t b2 = tf_bits(k2a, k2b, ctr);
            float u2 = __uint_as_float((b2 >> 9) | 0x3f800000u) - 1.0f;
            float eg = -__fdividef(1.0f, __nv_logf(fmaxf(TINYF, u2 + TINYF)));
            nz[idx] = make_float2(g1, eg);
        }
        __syncthreads();   // join #1
        __syncthreads();   // join #2
    }
}

// ---------------------------------------------------------------------------
// Kernel 4: reduce partials; if top-2 gap < TAU, repair row with exact fp32
//   sims + exact gumbel. Normalize ws, gather z_q, write indices.
// ---------------------------------------------------------------------------
__global__ void finalize_kernel(const float* __restrict__ cb,
                                float* __restrict__ zq,
                                float* __restrict__ ws,
                                float* __restrict__ idxo,
                                uint32_t k1a, uint32_t k1b) {
    int n = blockIdx.x, t = threadIdx.x;
    __shared__ int   s_best;
    __shared__ float s_inv;
    __shared__ int   s_flag;
    if (t == 0) {
        float bm = g_pm[(size_t)n * NBN]; int bi = g_pi[(size_t)n * NBN];
        float m2 = g_p2[(size_t)n * NBN];
        float sum = g_ps[(size_t)n * NBN];
#pragma unroll
        for (int j = 1; j < NBN; j++) {
            float m = g_pm[(size_t)n * NBN + j];
            int   i = g_pi[(size_t)n * NBN + j];
            float q2 = g_p2[(size_t)n * NBN + j];
            float hi2 = fmaxf(fminf(bm, m), fmaxf(m2, q2));
            if (m > bm || (m == bm && i < bi)) { bm = m; bi = i; }
            m2 = hi2;
            sum += g_ps[(size_t)n * NBN + j];
        }
        s_best = bi;
        s_inv  = 1.0f / sum;
        s_flag = (bm - m2 < TAU) ? 1 : 0;
    }
    __syncthreads();

    if (s_flag) {
        // ---- exact repair: fp32 sims + exact gumbel for this row ----
        __shared__ float xs[512];
        __shared__ float sv8[8];
        __shared__ int   si8[8];
        for (int d = t; d < 512; d += 256) xs[d] = g_x[(size_t)n * 512 + d];
        __syncthreads();
        float bv = -3.4e38f; int bi = 0;
#pragma unroll
        for (int v = 0; v < 4; v++) {
            int col = t + v * 256;
            const float4* crow = (const float4*)(g_cn + (size_t)col * 512);
            float s = 0.f;
#pragma unroll 4
            for (int d4 = 0; d4 < 128; d4++) {
                float4 cv = crow[d4];
                s += xs[d4*4]*cv.x + xs[d4*4+1]*cv.y + xs[d4*4+2]*cv.z + xs[d4*4+3]*cv.w;
            }
            float v1 = s + gumbel_from_bits(
                tf_bits(k1a, k1b, (uint32_t)n * 1024u + (uint32_t)col));
            if (v1 > bv || (v1 == bv && col < bi)) { bv = v1; bi = col; }
        }
        for (int o = 16; o; o >>= 1) {
            float ov = __shfl_down_sync(0xffffffffu, bv, o);
            int   oi = __shfl_down_sync(0xffffffffu, bi, o);
            if (ov > bv || (ov == bv && oi < bi)) { bv = ov; bi = oi; }
        }
        if ((t & 31) == 0) { sv8[t >> 5] = bv; si8[t >> 5] = bi; }
        __syncthreads();
        if (t == 0) {
            float v0 = sv8[0]; int i0 = si8[0];
#pragma unroll
            for (int w = 1; w < 8; w++)
                if (sv8[w] > v0 || (sv8[w] == v0 && si8[w] < i0)) { v0 = sv8[w]; i0 = si8[w]; }
            s_best = i0;
        }
        __syncthreads();
    }

    int best = s_best; float inv = s_inv;

    float4* wrow = (float4*)(ws + (size_t)n * 1024);
    float4 v = wrow[t];
    v.x *= inv; v.y *= inv; v.z *= inv; v.w *= inv;
    wrow[t] = v;

    if (t < 128) {
        float4 c = *(const float4*)(cb + (size_t)best * D_DIM + t * 4);
        *(float4*)(zq + (size_t)n * D_DIM + t * 4) = c;
    }
    if (t == 0) idxo[n] = (float)best;
}

// ---------------------------------------------------------------------------
extern "C" void kernel_launch(void* const* d_in, const int* in_sizes, int n_in,
                              void* d_out, int out_size) {
    const float* st = (const float*)d_in[0];
    const float* ad = (const float*)d_in[1];
    const float* cb = (const float*)d_in[2];
    int N = in_sizes[0] / D_DIM;     // 32768
    int K = in_sizes[2] / D_DIM;     // 1024

    float* out  = (float*)d_out;
    float* zq   = out;                              // [N, D]
    float* ws   = out + (size_t)N * D_DIM;          // [N, K]
    float* idxo = ws + (size_t)N * K;               // [N, 1]

    // jax.random.key(42) -> (0,42); partitionable fold split
    uint32_t g1a = 0u, g1b = 0u;
    threefry2x32(0u, 42u, g1a, g1b);    // counter 0 -> gk1
    uint32_t g2a = 0u, g2b = 1u;
    threefry2x32(0u, 42u, g2a, g2b);    // counter 1 -> gk2

    cudaFuncSetAttribute(gemm_mma,
        cudaFuncAttributeMaxDynamicSharedMemorySize, SMEMB);

    norm_cb_fp<<<K / 16, 256>>>(cb);
    combine_fp<<<N / 16, 256>>>(st, ad);
    dim3 gg(K / 128, N / 128);          // (8, 256)
    gemm_mma<<<gg, 384, SMEMB>>>(ws, g1a, g1b, g2a, g2b);
    finalize_kernel<<<N, 256>>>(cb, zq, ws, idxo, g1a, g1b);
}

// round 14
// speedup vs baseline: 1.7122x; 1.3191x over previous
#include <cuda_runtime.h>
#include <cstdint>
#include <cstddef>

#define DI __device__ __forceinline__
static const int D_DIM = 512;
#define MAXN 32768
#define MAXK 1024
#define NBN  8
#define TAU  3e-3f

extern "C" __device__ float __nv_logf(float);

// Scratch (device globals; no allocation allowed)
__device__ uint32_t g_xf[(size_t)2048 * 64 * 128]; // 64MB: A tf32-hi blocks (mt16,kt8): lane->uint4
__device__ uint32_t g_cf[(size_t)128 * 64 * 64];   //  2MB: B tf32-hi blocks (nt8,kt8): lane->uint2
__device__ float g_x [(size_t)MAXN * D_DIM];       // 64MB fp32 combined input (repair)
__device__ float g_cn[(size_t)MAXK * D_DIM];       //  2MB fp32 normalized codebook (repair)
__device__ float g_pm[(size_t)MAXN * NBN];
__device__ int   g_pi[(size_t)MAXN * NBN];
__device__ float g_ps[(size_t)MAXN * NBN];
__device__ float g_p2[(size_t)MAXN * NBN];         // per-tile second max
__device__ int   g_rcount;
__device__ int   g_rlist[MAXN];

// ---------------------------------------------------------------------------
// Threefry-2x32 (exact JAX, partitionable mode)
// ---------------------------------------------------------------------------
__host__ __device__ inline uint32_t rotl32(uint32_t x, int r) {
    return (x << r) | (x >> (32 - r));
}
__host__ __device__ inline void threefry2x32(uint32_t k0, uint32_t k1,
                                             uint32_t& x0, uint32_t& x1) {
    uint32_t k2 = k0 ^ k1 ^ 0x1BD11BDAu;
    x0 += k0; x1 += k1;
#define TFR(r) { x0 += x1; x1 = rotl32(x1, r); x1 ^= x0; }
    TFR(13) TFR(15) TFR(26) TFR(6)
    x0 += k1; x1 += k2 + 1u;
    TFR(17) TFR(29) TFR(16) TFR(24)
    x0 += k2; x1 += k0 + 2u;
    TFR(13) TFR(15) TFR(26) TFR(6)
    x0 += k0; x1 += k1 + 3u;
    TFR(17) TFR(29) TFR(16) TFR(24)
    x0 += k1; x1 += k2 + 4u;
    TFR(13) TFR(15) TFR(26) TFR(6)
    x0 += k2; x1 += k0 + 5u;
#undef TFR
}
DI uint32_t tf_bits(uint32_t k0, uint32_t k1, uint32_t i) {
    uint32_t x0 = 0u, x1 = i;
    threefry2x32(k0, k1, x0, x1);
    return x0 ^ x1;
}
#define TINYF 1.17549435e-38f
// exact (repair path): bitwise-JAX gumbel
DI float gumbel_exact(uint32_t bits) {
    float u = __uint_as_float((bits >> 9) | 0x3f800000u) - 1.0f;
    float r = fmaxf(TINYF, u + TINYF);
    return -__nv_logf(-__nv_logf(r));
}

// ---------------------------------------------------------------------------
// low-level helpers
// ---------------------------------------------------------------------------
DI uint32_t smem_u32(const void* p) {
    uint32_t a;
    asm("{ .reg .u64 t; cvta.to.shared.u64 t, %1; cvt.u32.u64 %0, t; }"
        : "=r"(a) : "l"(p));
    return a;
}
DI uint32_t tf32h(float x) {
    uint32_t h; asm("cvt.rna.tf32.f32 %0, %1;" : "=r"(h) : "f"(x)); return h;
}
DI void cp16(uint32_t saddr, const void* g) {
    asm volatile("cp.async.cg.shared.global [%0], [%1], 16;"
                 :: "r"(saddr), "l"(g) : "memory");
}
#define CP_COMMIT() asm volatile("cp.async.commit_group;" ::: "memory")
#define CP_WAIT1()  asm volatile("cp.async.wait_group 1;" ::: "memory")
#define CP_WAIT0()  asm volatile("cp.async.wait_group 0;" ::: "memory")
DI void lds128(uint32_t* r, uint32_t addr) {
    asm volatile("ld.shared.v4.b32 {%0,%1,%2,%3}, [%4];"
        : "=r"(r[0]), "=r"(r[1]), "=r"(r[2]), "=r"(r[3]) : "r"(addr));
}
DI void lds64(uint32_t* r, uint32_t addr) {
    asm volatile("ld.shared.v2.b32 {%0,%1}, [%2];"
        : "=r"(r[0]), "=r"(r[1]) : "r"(addr));
}
DI void barx(int id, int n) {
    asm volatile("bar.sync %0, %1;" :: "r"(id), "r"(n) : "memory");
}
// m16n8k8 tf32 MMA (baseline PTX, drives tensor pipe on sm_103)
DI void mma8(float* d, const uint32_t* a, const uint32_t* b) {
    asm volatile(
        "mma.sync.aligned.m16n8k8.row.col.f32.tf32.tf32.f32 "
        "{%0,%1,%2,%3}, {%4,%5,%6,%7}, {%8,%9}, {%0,%1,%2,%3};"
        : "+f"(d[0]), "+f"(d[1]), "+f"(d[2]), "+f"(d[3])
        : "r"(a[0]), "r"(a[1]), "r"(a[2]), "r"(a[3]), "r"(b[0]), "r"(b[1]));
}

// ---------------------------------------------------------------------------
// Kernel 0: reset repair counter (graph-capturable)
// ---------------------------------------------------------------------------
__global__ void zero_kernel() { g_rcount = 0; }

// ---------------------------------------------------------------------------
// Kernel 1: codebook normalize -> g_cn fp32 + tf32-hi fragment-packed g_cf.
// ---------------------------------------------------------------------------
__global__ __launch_bounds__(256) void norm_cb_fp(const float* __restrict__ cb) {
    __shared__ float sc[16][516];
    int t = threadIdx.x, lane = t & 31, w = t >> 5;
    int R0 = blockIdx.x * 16;
#pragma unroll
    for (int rr = 0; rr < 2; rr++) {
        int row = 2 * w + rr;
        const float4* rp = (const float4*)(cb + (size_t)(R0 + row) * D_DIM);
        float4 v[4]; float ss = 0.f;
#pragma unroll
        for (int i = 0; i < 4; i++) {
            v[i] = rp[lane + 32 * i];
            ss += v[i].x * v[i].x + v[i].y * v[i].y + v[i].z * v[i].z + v[i].w * v[i].w;
        }
#pragma unroll
        for (int o = 16; o; o >>= 1) ss += __shfl_xor_sync(0xffffffffu, ss, o);
        float inv = 1.0f / fmaxf(sqrtf(ss), 1e-8f);
        float4* cn = (float4*)(g_cn + (size_t)(R0 + row) * D_DIM);
#pragma unroll
        for (int i = 0; i < 4; i++) {
            float4 q; q.x = v[i].x * inv; q.y = v[i].y * inv;
            q.z = v[i].z * inv; q.w = v[i].w * inv;
            cn[lane + 32 * i] = q;
            *(float4*)&sc[row][4 * (lane + 32 * i)] = q;
        }
    }
    __syncthreads();
    uint32_t* outp = g_cf + (size_t)blockIdx.x * 8192;
#pragma unroll
    for (int q = 0; q < 16; q++) {
        int p = t * 16 + q;
        int nt_l = p >> 11, pp = p & 2047;
        int kt = pp >> 5, ln = pp & 31;
        int nl = nt_l * 8 + (ln >> 2);
        int c  = kt * 8 + (ln & 3);
        uint2 o; o.x = tf32h(sc[nl][c]); o.y = tf32h(sc[nl][c + 4]);
        *(uint2*)(outp + (size_t)((nt_l * 64 + kt) * 64 + ln * 2)) = o;
    }
}

// ---------------------------------------------------------------------------
// Kernel 2: x = 0.5*st/||st|| + 0.5*ad/||ad|| -> g_x fp32 + tf32-hi g_xf.
// ---------------------------------------------------------------------------
__global__ __launch_bounds__(256) void combine_fp(const float* __restrict__ st,
                                                  const float* __restrict__ ad) {
    __shared__ float sx[16][516];
    int t = threadIdx.x, lane = t & 31, w = t >> 5;
    int R0 = blockIdx.x * 16;
#pragma unroll
    for (int rr = 0; rr < 2; rr++) {
        int row = 2 * w + rr;
        const float4* sp = (const float4*)(st + (size_t)(R0 + row) * D_DIM);
        const float4* ap = (const float4*)(ad + (size_t)(R0 + row) * D_DIM);
        float4 sv[4], av[4]; float ss = 0.f, aa = 0.f;
#pragma unroll
        for (int i = 0; i < 4; i++) {
            sv[i] = sp[lane + 32 * i];
            av[i] = ap[lane + 32 * i];
            ss += sv[i].x*sv[i].x + sv[i].y*sv[i].y + sv[i].z*sv[i].z + sv[i].w*sv[i].w;
            aa += av[i].x*av[i].x + av[i].y*av[i].y + av[i].z*av[i].z + av[i].w*av[i].w;
        }
#pragma unroll
        for (int o = 16; o; o >>= 1) {
            ss += __shfl_xor_sync(0xffffffffu, ss, o);
            aa += __shfl_xor_sync(0xffffffffu, aa, o);
        }
        float is = 0.5f / fmaxf(sqrtf(ss), 1e-8f);
        float ia = 0.5f / fmaxf(sqrtf(aa), 1e-8f);
        float4* xr = (float4*)(g_x + (size_t)(R0 + row) * D_DIM);
#pragma unroll
        for (int i = 0; i < 4; i++) {
            float4 q;
            q.x = sv[i].x * is + av[i].x * ia;
            q.y = sv[i].y * is + av[i].y * ia;
            q.z = sv[i].z * is + av[i].z * ia;
            q.w = sv[i].w * is + av[i].w * ia;
            xr[lane + 32 * i] = q;
            *(float4*)&sx[row][4 * (lane + 32 * i)] = q;
        }
    }
    __syncthreads();
    uint32_t* outp = g_xf + (size_t)blockIdx.x * 8192;
#pragma unroll
    for (int q = 0; q < 8; q++) {
        int p = t * 8 + q;
        int kt = p >> 5, ln = p & 31;
        int g = ln >> 2, c = kt * 8 + (ln & 3);
        uint4 H;
        H.x = tf32h(sx[g][c]);
        H.y = tf32h(sx[g + 8][c]);
        H.z = tf32h(sx[g][c + 4]);
        H.w = tf32h(sx[g + 8][c + 4]);
        *(uint4*)(outp + (size_t)p * 4) = H;
    }
}

// ---------------------------------------------------------------------------
// Kernel 3: 1xTF32 GEMM (128x128, BK=32, double-buffered) + 4 noise warps.
// ---------------------------------------------------------------------------
#define NZ_OFF 65536
#define SMEMB  196608

DI void issue_chunk(int c, int s, uint32_t sbase, int mtb, int ntb, int t) {
    int kt0 = c * 4;
#pragma unroll
    for (int i = 0; i < 4; i++) {          // A: 1024 x 16B
        int u = t + i * 256;
        int blk = u >> 5, off = u & 31;
        const uint32_t* g = g_xf
            + ((size_t)(mtb + (blk >> 2)) * 64 + kt0 + (blk & 3)) * 128 + off * 4;
        cp16(sbase + (uint32_t)(s * 16384 + blk * 512 + off * 16), g);
    }
#pragma unroll
    for (int i = 0; i < 4; i++) {          // B: 1024 x 16B
        int u = t + i * 256;
        int blk = u >> 4, off = u & 15;
        const uint32_t* g = g_cf
            + ((size_t)(ntb + (blk >> 2)) * 64 + kt0 + (blk & 3)) * 64 + off * 4;
        cp16(sbase + (uint32_t)(32768 + s * 16384 + blk * 256 + off * 16), g);
    }
}

__global__ __launch_bounds__(384, 1) void gemm_mma(
        float* __restrict__ ws,
        uint32_t k1a, uint32_t k1b, uint32_t k2a, uint32_t k2b) {
    extern __shared__ char smem[];
    const uint32_t sbase = smem_u32(smem);
    float2* nz = (float2*)(smem + NZ_OFF);
    const int t = threadIdx.x, lane = t & 31;
    const int mtb = blockIdx.y * 8, ntb = blockIdx.x * 16;
    const int bm = blockIdx.y * 128, bn = blockIdx.x * 128;

    if (t < 256) {
        // ================= HMMA GEMM role =================
        const int wid = t >> 5;
        const int wm = wid >> 1, wn = wid & 1;
        const int g = lane >> 2;

        float acc[16][4];
#pragma unroll
        for (int i = 0; i < 16; i++)
#pragma unroll
            for (int j = 0; j < 4; j++) acc[i][j] = 0.f;

        issue_chunk(0, 0, sbase, mtb, ntb, t);
        CP_COMMIT();
        issue_chunk(1, 1, sbase, mtb, ntb, t);
        CP_COMMIT();

        for (int c = 0; c < 16; c++) {
            if (c < 15) { CP_WAIT1(); } else { CP_WAIT0(); }
            barx(1, 256);
            const uint32_t AS = sbase + (uint32_t)((c & 1) * 16384);
            const uint32_t BS = sbase + (uint32_t)(32768 + (c & 1) * 16384);
#pragma unroll
            for (int ktl = 0; ktl < 4; ktl++) {
                uint32_t ah[2][4];
#pragma unroll
                for (int m = 0; m < 2; m++)
                    lds128(ah[m], AS + (uint32_t)(((wm * 2 + m) * 4 + ktl) * 512 + lane * 16));
#pragma unroll
                for (int g2 = 0; g2 < 2; g2++) {
#pragma unroll
                    for (int n4 = 0; n4 < 4; n4++) {
                        uint32_t bh[2];
                        lds64(bh, BS + (uint32_t)(((wn * 8 + g2 * 4 + n4) * 4 + ktl) * 256 + lane * 8));
#pragma unroll
                        for (int m = 0; m < 2; m++)
                            mma8(acc[m * 8 + g2 * 4 + n4], ah[m], bh);
                    }
                }
            }
            barx(1, 256);
            if (c + 2 < 16) {
                issue_chunk(c + 2, c & 1, sbase, mtb, ntb, t);
                CP_COMMIT();
            }
        }

        __syncthreads();   // join #1 with noise warps

        // ---- epilogue: top-2 argmax partials + exp-path into ws ----
        float rmax[4], rmax2[4], rsum[4]; int ridx[4];
#pragma unroll
        for (int m = 0; m < 2; m++)
#pragma unroll
        for (int h = 0; h < 2; h++) {
            int e = m * 2 + h;
            int rowloc = wm * 32 + m * 16 + h * 8 + g;
            int colb = wn * 64 + (lane & 3) * 2;
            int grow = bm + rowloc;
            float bmax = -3.4e38f, bmax2 = -3.4e38f; int bidx = 0; float bsum = 0.f;
            float* wrow = ws + (size_t)grow * 1024 + bn;
#pragma unroll
            for (int n = 0; n < 8; n++) {
                int ccl = colb + n * 8;
                float s0 = acc[m * 8 + n][h * 2];
                float s1 = acc[m * 8 + n][h * 2 + 1];
                float4 nv = *(float4*)&nz[rowloc * 128 + ccl];
                float v1a = s0 + nv.x;
                if (v1a > bmax) { bmax2 = bmax; bmax = v1a; bidx = bn + ccl; }
                else if (v1a > bmax2) bmax2 = v1a;
                float v1b = s1 + nv.z;
                if (v1b > bmax) { bmax2 = bmax; bmax = v1b; bidx = bn + ccl + 1; }
                else if (v1b > bmax2) bmax2 = v1b;
                float p0 = __expf(s0) * nv.y;
                float p1 = __expf(s1) * nv.w;
                bsum += p0 + p1;
                *(float2*)(wrow + ccl) = make_float2(p0, p1);
            }
#pragma unroll
            for (int o = 1; o <= 2; o <<= 1) {
                float om  = __shfl_xor_sync(0xffffffffu, bmax, o);
                int   oi  = __shfl_xor_sync(0xffffffffu, bidx, o);
                float om2 = __shfl_xor_sync(0xffffffffu, bmax2, o);
                float os  = __shfl_xor_sync(0xffffffffu, bsum, o);
                float hi2 = fmaxf(fminf(bmax, om), fmaxf(bmax2, om2));
                if (om > bmax || (om == bmax && oi < bidx)) { bmax = om; bidx = oi; }
                bmax2 = hi2;
                bsum += os;
            }
            rmax[e] = bmax; rmax2[e] = bmax2; ridx[e] = bidx; rsum[e] = bsum;
        }

        float* rm  = (float*)(smem);
        int*   ri  = (int*)  (smem + 1024);
        float* rs  = (float*)(smem + 2048);
        float* rm2 = (float*)(smem + 3072);
        if (wn == 1 && (lane & 3) == 0) {
#pragma unroll
            for (int e = 0; e < 4; e++) {
                int rl = wm * 32 + (e >> 1) * 16 + (e & 1) * 8 + g;
                rm[rl] = rmax[e]; ri[rl] = ridx[e]; rs[rl] = rsum[e]; rm2[rl] = rmax2[e];
            }
        }
        __syncthreads();   // join #2
        if (wn == 0 && (lane & 3) == 0) {
#pragma unroll
            for (int e = 0; e < 4; e++) {
                int rl = wm * 32 + (e >> 1) * 16 + (e & 1) * 8 + g;
                float om = rm[rl]; int oi = ri[rl]; float os = rs[rl]; float om2 = rm2[rl];
                float bmv = rmax[e]; int biv = ridx[e];
                float hi2 = fmaxf(fminf(bmv, om), fmaxf(rmax2[e], om2));
                if (om > bmv || (om == bmv && oi < biv)) { bmv = om; biv = oi; }
                size_t pidx = (size_t)(bm + rl) * NBN + blockIdx.x;
                g_pm[pidx] = bmv; g_pi[pidx] = biv;
                g_ps[pidx] = rsum[e] + os; g_p2[pidx] = hi2;
            }
        }
    } else {
        // ================= noise role: 16384 elems =================
        const int jj = t - 256;   // 0..127
#pragma unroll 2
        for (int it = 0; it < 128; it++) {
            int idx = it * 128 + jj;
            int row = idx >> 7, col = idx & 127;
            uint32_t ctr = (uint32_t)(bm + row) * 1024u + (uint32_t)(bn + col);
            uint32_t b1 = tf_bits(k1a, k1b, ctr);
            float u1 = __uint_as_float((b1 >> 9) | 0x3f800000u) - 1.0f;
            float m1 = -__nv_logf(fmaxf(TINYF, u1 + TINYF));   // precise inner
            float g1 = -__logf(m1);                            // fast outer (covered by TAU+repair)
            uint32_t b2 = tf_bits(k2a, k2b, ctr);
            float u2 = __uint_as_float((b2 >> 9) | 0x3f800000u) - 1.0f;
            float eg = -__fdividef(1.0f, __nv_logf(fmaxf(TINYF, u2 + TINYF)));
            nz[idx] = make_float2(g1, eg);
        }
        __syncthreads();   // join #1
        __syncthreads();   // join #2
    }
}

// ---------------------------------------------------------------------------
// Kernel 4 (lean): reduce partials; flag rows with gap < TAU into g_rlist;
//   provisional outputs for all rows.
// ---------------------------------------------------------------------------
__global__ void finalize_kernel(const float* __restrict__ cb,
                                float* __restrict__ zq,
                                float* __restrict__ ws,
                                float* __restrict__ idxo) {
    int n = blockIdx.x, t = threadIdx.x;
    __shared__ int   s_best;
    __shared__ float s_inv;
    if (t == 0) {
        float bm = g_pm[(size_t)n * NBN]; int bi = g_pi[(size_t)n * NBN];
        float m2 = g_p2[(size_t)n * NBN];
        float sum = g_ps[(size_t)n * NBN];
#pragma unroll
        for (int j = 1; j < NBN; j++) {
            float m = g_pm[(size_t)n * NBN + j];
            int   i = g_pi[(size_t)n * NBN + j];
            float q2 = g_p2[(size_t)n * NBN + j];
            float hi2 = fmaxf(fminf(bm, m), fmaxf(m2, q2));
            if (m > bm || (m == bm && i < bi)) { bm = m; bi = i; }
            m2 = hi2;
            sum += g_ps[(size_t)n * NBN + j];
        }
        s_best = bi;
        s_inv  = 1.0f / sum;
        if (bm - m2 < TAU) {
            int slot = atomicAdd(&g_rcount, 1);
            g_rlist[slot] = n;
        }
    }
    __syncthreads();
    int best = s_best; float inv = s_inv;

    float4* wrow = (float4*)(ws + (size_t)n * 1024);
    float4 v = wrow[t];
    v.x *= inv; v.y *= inv; v.z *= inv; v.w *= inv;
    wrow[t] = v;

    if (t < 128) {
        float4 c = *(const float4*)(cb + (size_t)best * D_DIM + t * 4);
        *(float4*)(zq + (size_t)n * D_DIM + t * 4) = c;
    }
    if (t == 0) idxo[n] = (float)best;
}

// ---------------------------------------------------------------------------
// Kernel 5: exact repair of flagged rows (fp32 sims + bitwise-exact gumbel).
// ---------------------------------------------------------------------------
__global__ __launch_bounds__(256) void repair_kernel(
        const float* __restrict__ cb,
        float* __restrict__ zq,
        float* __restrict__ idxo,
        uint32_t k1a, uint32_t k1b) {
    __shared__ float xs[512];
    __shared__ float sv8[8];
    __shared__ int   si8[8];
    __shared__ int   s_best;
    int cnt = g_rcount;
    int t = threadIdx.x;
    for (int it = blockIdx.x; it < cnt; it += gridDim.x) {
        int n = g_rlist[it];
        for (int d = t; d < 512; d += 256) xs[d] = g_x[(size_t)n * 512 + d];
        __syncthreads();
        float bv = -3.4e38f; int bi = 0;
#pragma unroll
        for (int v = 0; v < 4; v++) {
            int col = t + v * 256;
            const float4* crow = (const float4*)(g_cn + (size_t)col * 512);
            float s = 0.f;
#pragma unroll 8
            for (int d4 = 0; d4 < 128; d4++) {
                float4 cv = crow[d4];
                s += xs[d4*4]*cv.x + xs[d4*4+1]*cv.y + xs[d4*4+2]*cv.z + xs[d4*4+3]*cv.w;
            }
            float v1 = s + gumbel_exact(
                tf_bits(k1a, k1b, (uint32_t)n * 1024u + (uint32_t)col));
            if (v1 > bv || (v1 == bv && col < bi)) { bv = v1; bi = col; }
        }
        for (int o = 16; o; o >>= 1) {
            float ov = __shfl_down_sync(0xffffffffu, bv, o);
            int   oi = __shfl_down_sync(0xffffffffu, bi, o);
            if (ov > bv || (ov == bv && oi < bi)) { bv = ov; bi = oi; }
        }
        if ((t & 31) == 0) { sv8[t >> 5] = bv; si8[t >> 5] = bi; }
        __syncthreads();
        if (t == 0) {
            float v0 = sv8[0]; int i0 = si8[0];
#pragma unroll
            for (int w = 1; w < 8; w++)
                if (sv8[w] > v0 || (sv8[w] == v0 && si8[w] < i0)) { v0 = sv8[w]; i0 = si8[w]; }
            s_best = i0;
        }
        __syncthreads();
        int best = s_best;
        if (t < 128) {
            float4 c = *(const float4*)(cb + (size_t)best * D_DIM + t * 4);
            *(float4*)(zq + (size_t)n * D_DIM + t * 4) = c;
        }
        if (t == 0) idxo[n] = (float)best;
        __syncthreads();   // protect xs before next row
    }
}

// ---------------------------------------------------------------------------
extern "C" void kernel_launch(void* const* d_in, const int* in_sizes, int n_in,
                              void* d_out, int out_size) {
    const float* st = (const float*)d_in[0];
    const float* ad = (const float*)d_in[1];
    const float* cb = (const float*)d_in[2];
    int N = in_sizes[0] / D_DIM;     // 32768
    int K = in_sizes[2] / D_DIM;     // 1024

    float* out  = (float*)d_out;
    float* zq   = out;                              // [N, D]
    float* ws   = out + (size_t)N * D_DIM;          // [N, K]
    float* idxo = ws + (size_t)N * K;               // [N, 1]

    // jax.random.key(42) -> (0,42); partitionable fold split
    uint32_t g1a = 0u, g1b = 0u;
    threefry2x32(0u, 42u, g1a, g1b);    // counter 0 -> gk1
    uint32_t g2a = 0u, g2b = 1u;
    threefry2x32(0u, 42u, g2a, g2b);    // counter 1 -> gk2

    cudaFuncSetAttribute(gemm_mma,
        cudaFuncAttributeMaxDynamicSharedMemorySize, SMEMB);

    zero_kernel<<<1, 1>>>();
    norm_cb_fp<<<K / 16, 256>>>(cb);
    combine_fp<<<N / 16, 256>>>(st, ad);
    dim3 gg(K / 128, N / 128);          // (8, 256)
    gemm_mma<<<gg, 384, SMEMB>>>(ws, g1a, g1b, g2a, g2b);
    finalize_kernel<<<N, 256>>>(cb, zq, ws, idxo);
    repair_kernel<<<128, 256>>>(cb, zq, idxo, g1a, g1b);
}

// round 15
// speedup vs baseline: 1.7946x; 1.0481x over previous
#include <cuda_runtime.h>
#include <cstdint>
#include <cstddef>

#define DI __device__ __forceinline__
static const int D_DIM = 512;
#define MAXN 32768
#define MAXK 1024
#define NBN  8
#define TAU  3e-3f

extern "C" __device__ float __nv_logf(float);

// Scratch (device globals; no allocation allowed)
__device__ uint32_t g_xf[(size_t)2048 * 64 * 128]; // 64MB: A tf32-hi blocks (mt16,kt8): lane->uint4
__device__ uint32_t g_cf[(size_t)128 * 64 * 64];   //  2MB: B tf32-hi blocks (nt8,kt8): lane->uint2
__device__ float g_x [(size_t)MAXN * D_DIM];       // 64MB fp32 combined input (repair)
__device__ float g_cn[(size_t)MAXK * D_DIM];       //  2MB fp32 normalized codebook (repair)
__device__ float g_pm[(size_t)MAXN * NBN];
__device__ int   g_pi[(size_t)MAXN * NBN];
__device__ float g_ps[(size_t)MAXN * NBN];
__device__ float g_p2[(size_t)MAXN * NBN];         // per-tile second max
__device__ int   g_rcount;
__device__ int   g_rlist[MAXN];

// ---------------------------------------------------------------------------
// Threefry-2x32 (exact JAX, partitionable mode)
// ---------------------------------------------------------------------------
__host__ __device__ inline uint32_t rotl32(uint32_t x, int r) {
    return (x << r) | (x >> (32 - r));
}
__host__ __device__ inline void threefry2x32(uint32_t k0, uint32_t k1,
                                             uint32_t& x0, uint32_t& x1) {
    uint32_t k2 = k0 ^ k1 ^ 0x1BD11BDAu;
    x0 += k0; x1 += k1;
#define TFR(r) { x0 += x1; x1 = rotl32(x1, r); x1 ^= x0; }
    TFR(13) TFR(15) TFR(26) TFR(6)
    x0 += k1; x1 += k2 + 1u;
    TFR(17) TFR(29) TFR(16) TFR(24)
    x0 += k2; x1 += k0 + 2u;
    TFR(13) TFR(15) TFR(26) TFR(6)
    x0 += k0; x1 += k1 + 3u;
    TFR(17) TFR(29) TFR(16) TFR(24)
    x0 += k1; x1 += k2 + 4u;
    TFR(13) TFR(15) TFR(26) TFR(6)
    x0 += k2; x1 += k0 + 5u;
#undef TFR
}
DI uint32_t tf_bits(uint32_t k0, uint32_t k1, uint32_t i) {
    uint32_t x0 = 0u, x1 = i;
    threefry2x32(k0, k1, x0, x1);
    return x0 ^ x1;
}
#define TINYF 1.17549435e-38f
// exact (repair path): bitwise-JAX gumbel
DI float gumbel_exact(uint32_t bits) {
    float u = __uint_as_float((bits >> 9) | 0x3f800000u) - 1.0f;
    float r = fmaxf(TINYF, u + TINYF);
    return -__nv_logf(-__nv_logf(r));
}

// ---------------------------------------------------------------------------
// low-level helpers
// ---------------------------------------------------------------------------
DI uint32_t smem_u32(const void* p) {
    uint32_t a;
    asm("{ .reg .u64 t; cvta.to.shared.u64 t, %1; cvt.u32.u64 %0, t; }"
        : "=r"(a) : "l"(p));
    return a;
}
DI uint32_t tf32h(float x) {
    uint32_t h; asm("cvt.rna.tf32.f32 %0, %1;" : "=r"(h) : "f"(x)); return h;
}
DI void cp16(uint32_t saddr, const void* g) {
    asm volatile("cp.async.cg.shared.global [%0], [%1], 16;"
                 :: "r"(saddr), "l"(g) : "memory");
}
#define CP_COMMIT() asm volatile("cp.async.commit_group;" ::: "memory")
#define CP_WAIT1()  asm volatile("cp.async.wait_group 1;" ::: "memory")
#define CP_WAIT0()  asm volatile("cp.async.wait_group 0;" ::: "memory")
DI void lds128(uint32_t* r, uint32_t addr) {
    asm volatile("ld.shared.v4.b32 {%0,%1,%2,%3}, [%4];"
        : "=r"(r[0]), "=r"(r[1]), "=r"(r[2]), "=r"(r[3]) : "r"(addr));
}
DI void lds64(uint32_t* r, uint32_t addr) {
    asm volatile("ld.shared.v2.b32 {%0,%1}, [%2];"
        : "=r"(r[0]), "=r"(r[1]) : "r"(addr));
}
DI void barx(int id, int n) {
    asm volatile("bar.sync %0, %1;" :: "r"(id), "r"(n) : "memory");
}
// m16n8k8 tf32 MMA (baseline PTX, drives tensor pipe on sm_103)
DI void mma8(float* d, const uint32_t* a, const uint32_t* b) {
    asm volatile(
        "mma.sync.aligned.m16n8k8.row.col.f32.tf32.tf32.f32 "
        "{%0,%1,%2,%3}, {%4,%5,%6,%7}, {%8,%9}, {%0,%1,%2,%3};"
        : "+f"(d[0]), "+f"(d[1]), "+f"(d[2]), "+f"(d[3])
        : "r"(a[0]), "r"(a[1]), "r"(a[2]), "r"(a[3]), "r"(b[0]), "r"(b[1]));
}

// ---------------------------------------------------------------------------
// Kernel 0: reset repair counter (graph-capturable)
// ---------------------------------------------------------------------------
__global__ void zero_kernel() { g_rcount = 0; }

// ---------------------------------------------------------------------------
// Kernel 1: codebook normalize -> g_cn fp32 + tf32-hi fragment-packed g_cf.
// ---------------------------------------------------------------------------
__global__ __launch_bounds__(256) void norm_cb_fp(const float* __restrict__ cb) {
    __shared__ float sc[16][516];
    int t = threadIdx.x, lane = t & 31, w = t >> 5;
    int R0 = blockIdx.x * 16;
#pragma unroll
    for (int rr = 0; rr < 2; rr++) {
        int row = 2 * w + rr;
        const float4* rp = (const float4*)(cb + (size_t)(R0 + row) * D_DIM);
        float4 v[4]; float ss = 0.f;
#pragma unroll
        for (int i = 0; i < 4; i++) {
            v[i] = rp[lane + 32 * i];
            ss += v[i].x * v[i].x + v[i].y * v[i].y + v[i].z * v[i].z + v[i].w * v[i].w;
        }
#pragma unroll
        for (int o = 16; o; o >>= 1) ss += __shfl_xor_sync(0xffffffffu, ss, o);
        float inv = 1.0f / fmaxf(sqrtf(ss), 1e-8f);
        float4* cn = (float4*)(g_cn + (size_t)(R0 + row) * D_DIM);
#pragma unroll
        for (int i = 0; i < 4; i++) {
            float4 q; q.x = v[i].x * inv; q.y = v[i].y * inv;
            q.z = v[i].z * inv; q.w = v[i].w * inv;
            cn[lane + 32 * i] = q;
            *(float4*)&sc[row][4 * (lane + 32 * i)] = q;
        }
    }
    __syncthreads();
    uint32_t* outp = g_cf + (size_t)blockIdx.x * 8192;
#pragma unroll
    for (int q = 0; q < 16; q++) {
        int p = t * 16 + q;
        int nt_l = p >> 11, pp = p & 2047;
        int kt = pp >> 5, ln = pp & 31;
        int nl = nt_l * 8 + (ln >> 2);
        int c  = kt * 8 + (ln & 3);
        uint2 o; o.x = tf32h(sc[nl][c]); o.y = tf32h(sc[nl][c + 4]);
        *(uint2*)(outp + (size_t)((nt_l * 64 + kt) * 64 + ln * 2)) = o;
    }
}

// ---------------------------------------------------------------------------
// Kernel 2: x = 0.5*st/||st|| + 0.5*ad/||ad|| -> g_x fp32 + tf32-hi g_xf.
// ---------------------------------------------------------------------------
__global__ __launch_bounds__(256) void combine_fp(const float* __restrict__ st,
                                                  const float* __restrict__ ad) {
    __shared__ float sx[16][516];
    int t = threadIdx.x, lane = t & 31, w = t >> 5;
    int R0 = blockIdx.x * 16;
#pragma unroll
    for (int rr = 0; rr < 2; rr++) {
        int row = 2 * w + rr;
        const float4* sp = (const float4*)(st + (size_t)(R0 + row) * D_DIM);
        const float4* ap = (const float4*)(ad + (size_t)(R0 + row) * D_DIM);
        float4 sv[4], av[4]; float ss = 0.f, aa = 0.f;
#pragma unroll
        for (int i = 0; i < 4; i++) {
            sv[i] = sp[lane + 32 * i];
            av[i] = ap[lane + 32 * i];
            ss += sv[i].x*sv[i].x + sv[i].y*sv[i].y + sv[i].z*sv[i].z + sv[i].w*sv[i].w;
            aa += av[i].x*av[i].x + av[i].y*av[i].y + av[i].z*av[i].z + av[i].w*av[i].w;
        }
#pragma unroll
        for (int o = 16; o; o >>= 1) {
            ss += __shfl_xor_sync(0xffffffffu, ss, o);
            aa += __shfl_xor_sync(0xffffffffu, aa, o);
        }
        float is = 0.5f / fmaxf(sqrtf(ss), 1e-8f);
        float ia = 0.5f / fmaxf(sqrtf(aa), 1e-8f);
        float4* xr = (float4*)(g_x + (size_t)(R0 + row) * D_DIM);
#pragma unroll
        for (int i = 0; i < 4; i++) {
            float4 q;
            q.x = sv[i].x * is + av[i].x * ia;
            q.y = sv[i].y * is + av[i].y * ia;
            q.z = sv[i].z * is + av[i].z * ia;
            q.w = sv[i].w * is + av[i].w * ia;
            xr[lane + 32 * i] = q;
            *(float4*)&sx[row][4 * (lane + 32 * i)] = q;
        }
    }
    __syncthreads();
    uint32_t* outp = g_xf + (size_t)blockIdx.x * 8192;
#pragma unroll
    for (int q = 0; q < 8; q++) {
        int p = t * 8 + q;
        int kt = p >> 5, ln = p & 31;
        int g = ln >> 2, c = kt * 8 + (ln & 3);
        uint4 H;
        H.x = tf32h(sx[g][c]);
        H.y = tf32h(sx[g + 8][c]);
        H.z = tf32h(sx[g][c + 4]);
        H.w = tf32h(sx[g + 8][c + 4]);
        *(uint4*)(outp + (size_t)p * 4) = H;
    }
}

// ---------------------------------------------------------------------------
// Kernel 3: 1xTF32 GEMM (128x128, BK=32, double-buffered) + 8 noise warps.
//   512 threads: warps 0-7 HMMA (2/SMSP), warps 8-15 noise (2/SMSP -> alu
//   pipe saturated instead of 50%). Named barrier 1 scopes MMA warps only.
// ---------------------------------------------------------------------------
#define NZ_OFF 65536
#define SMEMB  196608

DI void issue_chunk(int c, int s, uint32_t sbase, int mtb, int ntb, int t) {
    int kt0 = c * 4;
#pragma unroll
    for (int i = 0; i < 4; i++) {          // A: 1024 x 16B
        int u = t + i * 256;
        int blk = u >> 5, off = u & 31;
        const uint32_t* g = g_xf
            + ((size_t)(mtb + (blk >> 2)) * 64 + kt0 + (blk & 3)) * 128 + off * 4;
        cp16(sbase + (uint32_t)(s * 16384 + blk * 512 + off * 16), g);
    }
#pragma unroll
    for (int i = 0; i < 4; i++) {          // B: 1024 x 16B
        int u = t + i * 256;
        int blk = u >> 4, off = u & 15;
        const uint32_t* g = g_cf
            + ((size_t)(ntb + (blk >> 2)) * 64 + kt0 + (blk & 3)) * 64 + off * 4;
        cp16(sbase + (uint32_t)(32768 + s * 16384 + blk * 256 + off * 16), g);
    }
}

__global__ __launch_bounds__(512, 1) void gemm_mma(
        float* __restrict__ ws,
        uint32_t k1a, uint32_t k1b, uint32_t k2a, uint32_t k2b) {
    extern __shared__ char smem[];
    const uint32_t sbase = smem_u32(smem);
    float2* nz = (float2*)(smem + NZ_OFF);
    const int t = threadIdx.x, lane = t & 31;
    const int mtb = blockIdx.y * 8, ntb = blockIdx.x * 16;
    const int bm = blockIdx.y * 128, bn = blockIdx.x * 128;

    if (t < 256) {
        // ================= HMMA GEMM role =================
        const int wid = t >> 5;
        const int wm = wid >> 1, wn = wid & 1;
        const int g = lane >> 2;

        float acc[16][4];
#pragma unroll
        for (int i = 0; i < 16; i++)
#pragma unroll
            for (int j = 0; j < 4; j++) acc[i][j] = 0.f;

        issue_chunk(0, 0, sbase, mtb, ntb, t);
        CP_COMMIT();
        issue_chunk(1, 1, sbase, mtb, ntb, t);
        CP_COMMIT();

        for (int c = 0; c < 16; c++) {
            if (c < 15) { CP_WAIT1(); } else { CP_WAIT0(); }
            barx(1, 256);
            const uint32_t AS = sbase + (uint32_t)((c & 1) * 16384);
            const uint32_t BS = sbase + (uint32_t)(32768 + (c & 1) * 16384);
#pragma unroll
            for (int ktl = 0; ktl < 4; ktl++) {
                uint32_t ah[2][4];
#pragma unroll
                for (int m = 0; m < 2; m++)
                    lds128(ah[m], AS + (uint32_t)(((wm * 2 + m) * 4 + ktl) * 512 + lane * 16));
#pragma unroll
                for (int g2 = 0; g2 < 2; g2++) {
#pragma unroll
                    for (int n4 = 0; n4 < 4; n4++) {
                        uint32_t bh[2];
                        lds64(bh, BS + (uint32_t)(((wn * 8 + g2 * 4 + n4) * 4 + ktl) * 256 + lane * 8));
#pragma unroll
                        for (int m = 0; m < 2; m++)
                            mma8(acc[m * 8 + g2 * 4 + n4], ah[m], bh);
                    }
                }
            }
            barx(1, 256);
            if (c + 2 < 16) {
                issue_chunk(c + 2, c & 1, sbase, mtb, ntb, t);
                CP_COMMIT();
            }
        }

        __syncthreads();   // join #1 with noise warps

        // ---- epilogue: top-2 argmax partials + exp-path into ws ----
        float rmax[4], rmax2[4], rsum[4]; int ridx[4];
#pragma unroll
        for (int m = 0; m < 2; m++)
#pragma unroll
        for (int h = 0; h < 2; h++) {
            int e = m * 2 + h;
            int rowloc = wm * 32 + m * 16 + h * 8 + g;
            int colb = wn * 64 + (lane & 3) * 2;
            int grow = bm + rowloc;
            float bmax = -3.4e38f, bmax2 = -3.4e38f; int bidx = 0; float bsum = 0.f;
            float* wrow = ws + (size_t)grow * 1024 + bn;
#pragma unroll
            for (int n = 0; n < 8; n++) {
                int ccl = colb + n * 8;
                float s0 = acc[m * 8 + n][h * 2];
                float s1 = acc[m * 8 + n][h * 2 + 1];
                float4 nv = *(float4*)&nz[rowloc * 128 + ccl];
                float v1a = s0 + nv.x;
                if (v1a > bmax) { bmax2 = bmax; bmax = v1a; bidx = bn + ccl; }
                else if (v1a > bmax2) bmax2 = v1a;
                float v1b = s1 + nv.z;
                if (v1b > bmax) { bmax2 = bmax; bmax = v1b; bidx = bn + ccl + 1; }
                else if (v1b > bmax2) bmax2 = v1b;
                float p0 = __expf(s0) * nv.y;
                float p1 = __expf(s1) * nv.w;
                bsum += p0 + p1;
                *(float2*)(wrow + ccl) = make_float2(p0, p1);
            }
#pragma unroll
            for (int o = 1; o <= 2; o <<= 1) {
                float om  = __shfl_xor_sync(0xffffffffu, bmax, o);
                int   oi  = __shfl_xor_sync(0xffffffffu, bidx, o);
                float om2 = __shfl_xor_sync(0xffffffffu, bmax2, o);
                float os  = __shfl_xor_sync(0xffffffffu, bsum, o);
                float hi2 = fmaxf(fminf(bmax, om), fmaxf(bmax2, om2));
                if (om > bmax || (om == bmax && oi < bidx)) { bmax = om; bidx = oi; }
                bmax2 = hi2;
                bsum += os;
            }
            rmax[e] = bmax; rmax2[e] = bmax2; ridx[e] = bidx; rsum[e] = bsum;
        }

        float* rm  = (float*)(smem);
        int*   ri  = (int*)  (smem + 1024);
        float* rs  = (float*)(smem + 2048);
        float* rm2 = (float*)(smem + 3072);
        if (wn == 1 && (lane & 3) == 0) {
#pragma unroll
            for (int e = 0; e < 4; e++) {
                int rl = wm * 32 + (e >> 1) * 16 + (e & 1) * 8 + g;
                rm[rl] = rmax[e]; ri[rl] = ridx[e]; rs[rl] = rsum[e]; rm2[rl] = rmax2[e];
            }
        }
        __syncthreads();   // join #2
        if (wn == 0 && (lane & 3) == 0) {
#pragma unroll
            for (int e = 0; e < 4; e++) {
                int rl = wm * 32 + (e >> 1) * 16 + (e & 1) * 8 + g;
                float om = rm[rl]; int oi = ri[rl]; float os = rs[rl]; float om2 = rm2[rl];
                float bmv = rmax[e]; int biv = ridx[e];
                float hi2 = fmaxf(fminf(bmv, om), fmaxf(rmax2[e], om2));
                if (om > bmv || (om == bmv && oi < biv)) { bmv = om; biv = oi; }
                size_t pidx = (size_t)(bm + rl) * NBN + blockIdx.x;
                g_pm[pidx] = bmv; g_pi[pidx] = biv;
                g_ps[pidx] = rsum[e] + os; g_p2[pidx] = hi2;
            }
        }
    } else {
        // ================= noise role: 16384 elems, 8 warps =================
        const int jj = t - 256;   // 0..255
#pragma unroll 2
        for (int it = 0; it < 64; it++) {
            int idx = it * 256 + jj;
            int row = idx >> 7, col = idx & 127;
            uint32_t ctr = (uint32_t)(bm + row) * 1024u + (uint32_t)(bn + col);
            uint32_t b1 = tf_bits(k1a, k1b, ctr);
            float u1 = __uint_as_float((b1 >> 9) | 0x3f800000u) - 1.0f;
            float m1 = -__nv_logf(fmaxf(TINYF, u1 + TINYF));   // precise inner
            float g1 = -__logf(m1);                            // fast outer (covered by TAU+repair)
            uint32_t b2 = tf_bits(k2a, k2b, ctr);
            float u2 = __uint_as_float((b2 >> 9) | 0x3f800000u) - 1.0f;
            float eg = -__fdividef(1.0f, __nv_logf(fmaxf(TINYF, u2 + TINYF)));
            nz[idx] = make_float2(g1, eg);
        }
        __syncthreads();   // join #1
        __syncthreads();   // join #2
    }
}

// ---------------------------------------------------------------------------
// Kernel 4 (lean): reduce partials; flag rows with gap < TAU into g_rlist;
//   provisional outputs for all rows.
// ---------------------------------------------------------------------------
__global__ void finalize_kernel(const float* __restrict__ cb,
                                float* __restrict__ zq,
                                float* __restrict__ ws,
                                float* __restrict__ idxo) {
    int n = blockIdx.x, t = threadIdx.x;
    __shared__ int   s_best;
    __shared__ float s_inv;
    if (t == 0) {
        float bm = g_pm[(size_t)n * NBN]; int bi = g_pi[(size_t)n * NBN];
        float m2 = g_p2[(size_t)n * NBN];
        float sum = g_ps[(size_t)n * NBN];
#pragma unroll
        for (int j = 1; j < NBN; j++) {
            float m = g_pm[(size_t)n * NBN + j];
            int   i = g_pi[(size_t)n * NBN + j];
            float q2 = g_p2[(size_t)n * NBN + j];
            float hi2 = fmaxf(fminf(bm, m), fmaxf(m2, q2));
            if (m > bm || (m == bm && i < bi)) { bm = m; bi = i; }
            m2 = hi2;
            sum += g_ps[(size_t)n * NBN + j];
        }
        s_best = bi;
        s_inv  = 1.0f / sum;
        if (bm - m2 < TAU) {
            int slot = atomicAdd(&g_rcount, 1);
            g_rlist[slot] = n;
        }
    }
    __syncthreads();
    int best = s_best; float inv = s_inv;

    float4* wrow = (float4*)(ws + (size_t)n * 1024);
    float4 v = wrow[t];
    v.x *= inv; v.y *= inv; v.z *= inv; v.w *= inv;
    wrow[t] = v;

    if (t < 128) {
        float4 c = *(const float4*)(cb + (size_t)best * D_DIM + t * 4);
        *(float4*)(zq + (size_t)n * D_DIM + t * 4) = c;
    }
    if (t == 0) idxo[n] = (float)best;
}

// ---------------------------------------------------------------------------
// Kernel 5: exact repair of flagged rows (fp32 sims + bitwise-exact gumbel).
// ---------------------------------------------------------------------------
__global__ __launch_bounds__(256) void repair_kernel(
        const float* __restrict__ cb,
        float* __restrict__ zq,
        float* __restrict__ idxo,
        uint32_t k1a, uint32_t k1b) {
    __shared__ float xs[512];
    __shared__ float sv8[8];
    __shared__ int   si8[8];
    __shared__ int   s_best;
    int cnt = g_rcount;
    int t = threadIdx.x;
    for (int it = blockIdx.x; it < cnt; it += gridDim.x) {
        int n = g_rlist[it];
        for (int d = t; d < 512; d += 256) xs[d] = g_x[(size_t)n * 512 + d];
        __syncthreads();
        float bv = -3.4e38f; int bi = 0;
#pragma unroll
        for (int v = 0; v < 4; v++) {
            int col = t + v * 256;
            const float4* crow = (const float4*)(g_cn + (size_t)col * 512);
            float s = 0.f;
#pragma unroll 8
            for (int d4 = 0; d4 < 128; d4++) {
                float4 cv = crow[d4];
                s += xs[d4*4]*cv.x + xs[d4*4+1]*cv.y + xs[d4*4+2]*cv.z + xs[d4*4+3]*cv.w;
            }
            float v1 = s + gumbel_exact(
                tf_bits(k1a, k1b, (uint32_t)n * 1024u + (uint32_t)col));
            if (v1 > bv || (v1 == bv && col < bi)) { bv = v1; bi = col; }
        }
        for (int o = 16; o; o >>= 1) {
            float ov = __shfl_down_sync(0xffffffffu, bv, o);
            int   oi = __shfl_down_sync(0xffffffffu, bi, o);
            if (ov > bv || (ov == bv && oi < bi)) { bv = ov; bi = oi; }
        }
        if ((t & 31) == 0) { sv8[t >> 5] = bv; si8[t >> 5] = bi; }
        __syncthreads();
        if (t == 0) {
            float v0 = sv8[0]; int i0 = si8[0];
#pragma unroll
            for (int w = 1; w < 8; w++)
                if (sv8[w] > v0 || (sv8[w] == v0 && si8[w] < i0)) { v0 = sv8[w]; i0 = si8[w]; }
            s_best = i0;
        }
        __syncthreads();
        int best = s_best;
        if (t < 128) {
            float4 c = *(const float4*)(cb + (size_t)best * D_DIM + t * 4);
            *(float4*)(zq + (size_t)n * D_DIM + t * 4) = c;
        }
        if (t == 0) idxo[n] = (float)best;
        __syncthreads();   // protect xs before next row
    }
}

// ---------------------------------------------------------------------------
extern "C" void kernel_launch(void* const* d_in, const int* in_sizes, int n_in,
                              void* d_out, int out_size) {
    const float* st = (const float*)d_in[0];
    const float* ad = (const float*)d_in[1];
    const float* cb = (const float*)d_in[2];
    int N = in_sizes[0] / D_DIM;     // 32768
    int K = in_sizes[2] / D_DIM;     // 1024

    float* out  = (float*)d_out;
    float* zq   = out;                              // [N, D]
    float* ws   = out + (size_t)N * D_DIM;          // [N, K]
    float* idxo = ws + (size_t)N * K;               // [N, 1]

    // jax.random.key(42) -> (0,42); partitionable fold split
    uint32_t g1a = 0u, g1b = 0u;
    threefry2x32(0u, 42u, g1a, g1b);    // counter 0 -> gk1
    uint32_t g2a = 0u, g2b = 1u;
    threefry2x32(0u, 42u, g2a, g2b);    // counter 1 -> gk2

    cudaFuncSetAttribute(gemm_mma,
        cudaFuncAttributeMaxDynamicSharedMemorySize, SMEMB);

    zero_kernel<<<1, 1>>>();
    norm_cb_fp<<<K / 16, 256>>>(cb);
    combine_fp<<<N / 16, 256>>>(st, ad);
    dim3 gg(K / 128, N / 128);          // (8, 256)
    gemm_mma<<<gg, 512, SMEMB>>>(ws, g1a, g1b, g2a, g2b);
    finalize_kernel<<<N, 256>>>(cb, zq, ws, idxo);
    repair_kernel<<<128, 256>>>(cb, zq, idxo, g1a, g1b);
}

// round 16
// speedup vs baseline: 1.7954x; 1.0005x over previous
#include <cuda_runtime.h>
#include <cstdint>
#include <cstddef>

#define DI __device__ __forceinline__
static const int D_DIM = 512;
#define MAXN 32768
#define MAXK 1024
#define NBN  8
#define TAU  3e-3f

extern "C" __device__ float __nv_logf(float);

// Scratch (device globals; no allocation allowed)
__device__ uint32_t g_xf[(size_t)2048 * 64 * 128]; // 64MB: A tf32-hi blocks (mt16,kt8): lane->uint4
__device__ uint32_t g_cf[(size_t)128 * 64 * 64];   //  2MB: B tf32-hi blocks (nt8,kt8): lane->uint2
__device__ float g_x [(size_t)MAXN * D_DIM];       // 64MB fp32 combined input (repair)
__device__ float g_cn[(size_t)MAXK * D_DIM];       //  2MB fp32 normalized codebook (repair)
__device__ float g_pm[(size_t)MAXN * NBN];
__device__ int   g_pi[(size_t)MAXN * NBN];
__device__ float g_ps[(size_t)MAXN * NBN];
__device__ float g_p2[(size_t)MAXN * NBN];         // per-tile second max
__device__ int   g_rcount;
__device__ int   g_rlist[MAXN];

// ---------------------------------------------------------------------------
// Threefry-2x32 (exact JAX, partitionable mode)
// ---------------------------------------------------------------------------
__host__ __device__ inline uint32_t rotl32(uint32_t x, int r) {
    return (x << r) | (x >> (32 - r));
}
__host__ __device__ inline void threefry2x32(uint32_t k0, uint32_t k1,
                                             uint32_t& x0, uint32_t& x1) {
    uint32_t k2 = k0 ^ k1 ^ 0x1BD11BDAu;
    x0 += k0; x1 += k1;
#define TFR(r) { x0 += x1; x1 = rotl32(x1, r); x1 ^= x0; }
    TFR(13) TFR(15) TFR(26) TFR(6)
    x0 += k1; x1 += k2 + 1u;
    TFR(17) TFR(29) TFR(16) TFR(24)
    x0 += k2; x1 += k0 + 2u;
    TFR(13) TFR(15) TFR(26) TFR(6)
    x0 += k0; x1 += k1 + 3u;
    TFR(17) TFR(29) TFR(16) TFR(24)
    x0 += k1; x1 += k2 + 4u;
    TFR(13) TFR(15) TFR(26) TFR(6)
    x0 += k2; x1 += k0 + 5u;
#undef TFR
}
DI uint32_t tf_bits(uint32_t k0, uint32_t k1, uint32_t i) {
    uint32_t x0 = 0u, x1 = i;
    threefry2x32(k0, k1, x0, x1);
    return x0 ^ x1;
}
#define TINYF 1.17549435e-38f
// exact (repair path): bitwise-JAX gumbel
DI float gumbel_exact(uint32_t bits) {
    float u = __uint_as_float((bits >> 9) | 0x3f800000u) - 1.0f;
    float r = fmaxf(TINYF, u + TINYF);
    return -__nv_logf(-__nv_logf(r));
}

// ---------------------------------------------------------------------------
// low-level helpers
// ---------------------------------------------------------------------------
DI uint32_t smem_u32(const void* p) {
    uint32_t a;
    asm("{ .reg .u64 t; cvta.to.shared.u64 t, %1; cvt.u32.u64 %0, t; }"
        : "=r"(a) : "l"(p));
    return a;
}
DI uint32_t tf32h(float x) {
    uint32_t h; asm("cvt.rna.tf32.f32 %0, %1;" : "=r"(h) : "f"(x)); return h;
}
DI void cp16(uint32_t saddr, const void* g) {
    asm volatile("cp.async.cg.shared.global [%0], [%1], 16;"
                 :: "r"(saddr), "l"(g) : "memory");
}
#define CP_COMMIT() asm volatile("cp.async.commit_group;" ::: "memory")
#define CP_WAIT1()  asm volatile("cp.async.wait_group 1;" ::: "memory")
#define CP_WAIT0()  asm volatile("cp.async.wait_group 0;" ::: "memory")
DI void lds128(uint32_t* r, uint32_t addr) {
    asm volatile("ld.shared.v4.b32 {%0,%1,%2,%3}, [%4];"
        : "=r"(r[0]), "=r"(r[1]), "=r"(r[2]), "=r"(r[3]) : "r"(addr));
}
DI void lds64(uint32_t* r, uint32_t addr) {
    asm volatile("ld.shared.v2.b32 {%0,%1}, [%2];"
        : "=r"(r[0]), "=r"(r[1]) : "r"(addr));
}
DI void barx(int id, int n) {
    asm volatile("bar.sync %0, %1;" :: "r"(id), "r"(n) : "memory");
}
// m16n8k8 tf32 MMA (baseline PTX, drives tensor pipe on sm_103)
DI void mma8(float* d, const uint32_t* a, const uint32_t* b) {
    asm volatile(
        "mma.sync.aligned.m16n8k8.row.col.f32.tf32.tf32.f32 "
        "{%0,%1,%2,%3}, {%4,%5,%6,%7}, {%8,%9}, {%0,%1,%2,%3};"
        : "+f"(d[0]), "+f"(d[1]), "+f"(d[2]), "+f"(d[3])
        : "r"(a[0]), "r"(a[1]), "r"(a[2]), "r"(a[3]), "r"(b[0]), "r"(b[1]));
}

// ---------------------------------------------------------------------------
// Kernel 0: reset repair counter (graph-capturable)
// ---------------------------------------------------------------------------
__global__ void zero_kernel() { g_rcount = 0; }

// ---------------------------------------------------------------------------
// Kernel 1: codebook normalize -> g_cn fp32 + tf32-hi fragment-packed g_cf.
// ---------------------------------------------------------------------------
__global__ __launch_bounds__(256) void norm_cb_fp(const float* __restrict__ cb) {
    __shared__ float sc[16][516];
    int t = threadIdx.x, lane = t & 31, w = t >> 5;
    int R0 = blockIdx.x * 16;
#pragma unroll
    for (int rr = 0; rr < 2; rr++) {
        int row = 2 * w + rr;
        const float4* rp = (const float4*)(cb + (size_t)(R0 + row) * D_DIM);
        float4 v[4]; float ss = 0.f;
#pragma unroll
        for (int i = 0; i < 4; i++) {
            v[i] = rp[lane + 32 * i];
            ss += v[i].x * v[i].x + v[i].y * v[i].y + v[i].z * v[i].z + v[i].w * v[i].w;
        }
#pragma unroll
        for (int o = 16; o; o >>= 1) ss += __shfl_xor_sync(0xffffffffu, ss, o);
        float inv = 1.0f / fmaxf(sqrtf(ss), 1e-8f);
        float4* cn = (float4*)(g_cn + (size_t)(R0 + row) * D_DIM);
#pragma unroll
        for (int i = 0; i < 4; i++) {
            float4 q; q.x = v[i].x * inv; q.y = v[i].y * inv;
            q.z = v[i].z * inv; q.w = v[i].w * inv;
            cn[lane + 32 * i] = q;
            *(float4*)&sc[row][4 * (lane + 32 * i)] = q;
        }
    }
    __syncthreads();
    uint32_t* outp = g_cf + (size_t)blockIdx.x * 8192;
#pragma unroll
    for (int q = 0; q < 16; q++) {
        int p = t * 16 + q;
        int nt_l = p >> 11, pp = p & 2047;
        int kt = pp >> 5, ln = pp & 31;
        int nl = nt_l * 8 + (ln >> 2);
        int c  = kt * 8 + (ln & 3);
        uint2 o; o.x = tf32h(sc[nl][c]); o.y = tf32h(sc[nl][c + 4]);
        *(uint2*)(outp + (size_t)((nt_l * 64 + kt) * 64 + ln * 2)) = o;
    }
}

// ---------------------------------------------------------------------------
// Kernel 2: x = 0.5*st/||st|| + 0.5*ad/||ad|| -> g_x fp32 + tf32-hi g_xf.
// ---------------------------------------------------------------------------
__global__ __launch_bounds__(256) void combine_fp(const float* __restrict__ st,
                                                  const float* __restrict__ ad) {
    __shared__ float sx[16][516];
    int t = threadIdx.x, lane = t & 31, w = t >> 5;
    int R0 = blockIdx.x * 16;
#pragma unroll
    for (int rr = 0; rr < 2; rr++) {
        int row = 2 * w + rr;
        const float4* sp = (const float4*)(st + (size_t)(R0 + row) * D_DIM);
        const float4* ap = (const float4*)(ad + (size_t)(R0 + row) * D_DIM);
        float4 sv[4], av[4]; float ss = 0.f, aa = 0.f;
#pragma unroll
        for (int i = 0; i < 4; i++) {
            sv[i] = sp[lane + 32 * i];
            av[i] = ap[lane + 32 * i];
            ss += sv[i].x*sv[i].x + sv[i].y*sv[i].y + sv[i].z*sv[i].z + sv[i].w*sv[i].w;
            aa += av[i].x*av[i].x + av[i].y*av[i].y + av[i].z*av[i].z + av[i].w*av[i].w;
        }
#pragma unroll
        for (int o = 16; o; o >>= 1) {
            ss += __shfl_xor_sync(0xffffffffu, ss, o);
            aa += __shfl_xor_sync(0xffffffffu, aa, o);
        }
        float is = 0.5f / fmaxf(sqrtf(ss), 1e-8f);
        float ia = 0.5f / fmaxf(sqrtf(aa), 1e-8f);
        float4* xr = (float4*)(g_x + (size_t)(R0 + row) * D_DIM);
#pragma unroll
        for (int i = 0; i < 4; i++) {
            float4 q;
            q.x = sv[i].x * is + av[i].x * ia;
            q.y = sv[i].y * is + av[i].y * ia;
            q.z = sv[i].z * is + av[i].z * ia;
            q.w = sv[i].w * is + av[i].w * ia;
            xr[lane + 32 * i] = q;
            *(float4*)&sx[row][4 * (lane + 32 * i)] = q;
        }
    }
    __syncthreads();
    uint32_t* outp = g_xf + (size_t)blockIdx.x * 8192;
#pragma unroll
    for (int q = 0; q < 8; q++) {
        int p = t * 8 + q;
        int kt = p >> 5, ln = p & 31;
        int g = ln >> 2, c = kt * 8 + (ln & 3);
        uint4 H;
        H.x = tf32h(sx[g][c]);
        H.y = tf32h(sx[g + 8][c]);
        H.z = tf32h(sx[g][c + 4]);
        H.w = tf32h(sx[g + 8][c + 4]);
        *(uint4*)(outp + (size_t)p * 4) = H;
    }
}

// ---------------------------------------------------------------------------
// Kernel 3: 1xTF32 GEMM (128x128, BK=32, double-buffered) + 8 noise warps.
//   Noise loop unrolled 4x (8 independent cipher chains/warp) and eg uses
//   fast MUFU log (R8-proven deterministic 2.9e-4) to cut chain latency.
// ---------------------------------------------------------------------------
#define NZ_OFF 65536
#define SMEMB  196608

DI void issue_chunk(int c, int s, uint32_t sbase, int mtb, int ntb, int t) {
    int kt0 = c * 4;
#pragma unroll
    for (int i = 0; i < 4; i++) {          // A: 1024 x 16B
        int u = t + i * 256;
        int blk = u >> 5, off = u & 31;
        const uint32_t* g = g_xf
            + ((size_t)(mtb + (blk >> 2)) * 64 + kt0 + (blk & 3)) * 128 + off * 4;
        cp16(sbase + (uint32_t)(s * 16384 + blk * 512 + off * 16), g);
    }
#pragma unroll
    for (int i = 0; i < 4; i++) {          // B: 1024 x 16B
        int u = t + i * 256;
        int blk = u >> 4, off = u & 15;
        const uint32_t* g = g_cf
            + ((size_t)(ntb + (blk >> 2)) * 64 + kt0 + (blk & 3)) * 64 + off * 4;
        cp16(sbase + (uint32_t)(32768 + s * 16384 + blk * 256 + off * 16), g);
    }
}

__global__ __launch_bounds__(512, 1) void gemm_mma(
        float* __restrict__ ws,
        uint32_t k1a, uint32_t k1b, uint32_t k2a, uint32_t k2b) {
    extern __shared__ char smem[];
    const uint32_t sbase = smem_u32(smem);
    float2* nz = (float2*)(smem + NZ_OFF);
    const int t = threadIdx.x, lane = t & 31;
    const int mtb = blockIdx.y * 8, ntb = blockIdx.x * 16;
    const int bm = blockIdx.y * 128, bn = blockIdx.x * 128;

    if (t < 256) {
        // ================= HMMA GEMM role =================
        const int wid = t >> 5;
        const int wm = wid >> 1, wn = wid & 1;
        const int g = lane >> 2;

        float acc[16][4];
#pragma unroll
        for (int i = 0; i < 16; i++)
#pragma unroll
            for (int j = 0; j < 4; j++) acc[i][j] = 0.f;

        issue_chunk(0, 0, sbase, mtb, ntb, t);
        CP_COMMIT();
        issue_chunk(1, 1, sbase, mtb, ntb, t);
        CP_COMMIT();

        for (int c = 0; c < 16; c++) {
            if (c < 15) { CP_WAIT1(); } else { CP_WAIT0(); }
            barx(1, 256);
            const uint32_t AS = sbase + (uint32_t)((c & 1) * 16384);
            const uint32_t BS = sbase + (uint32_t)(32768 + (c & 1) * 16384);
#pragma unroll
            for (int ktl = 0; ktl < 4; ktl++) {
                uint32_t ah[2][4];
#pragma unroll
                for (int m = 0; m < 2; m++)
                    lds128(ah[m], AS + (uint32_t)(((wm * 2 + m) * 4 + ktl) * 512 + lane * 16));
#pragma unroll
                for (int g2 = 0; g2 < 2; g2++) {
#pragma unroll
                    for (int n4 = 0; n4 < 4; n4++) {
                        uint32_t bh[2];
                        lds64(bh, BS + (uint32_t)(((wn * 8 + g2 * 4 + n4) * 4 + ktl) * 256 + lane * 8));
#pragma unroll
                        for (int m = 0; m < 2; m++)
                            mma8(acc[m * 8 + g2 * 4 + n4], ah[m], bh);
                    }
                }
            }
            barx(1, 256);
            if (c + 2 < 16) {
                issue_chunk(c + 2, c & 1, sbase, mtb, ntb, t);
                CP_COMMIT();
            }
        }

        __syncthreads();   // join #1 with noise warps

        // ---- epilogue: top-2 argmax partials + exp-path into ws ----
        float rmax[4], rmax2[4], rsum[4]; int ridx[4];
#pragma unroll
        for (int m = 0; m < 2; m++)
#pragma unroll
        for (int h = 0; h < 2; h++) {
            int e = m * 2 + h;
            int rowloc = wm * 32 + m * 16 + h * 8 + g;
            int colb = wn * 64 + (lane & 3) * 2;
            int grow = bm + rowloc;
            float bmax = -3.4e38f, bmax2 = -3.4e38f; int bidx = 0; float bsum = 0.f;
            float* wrow = ws + (size_t)grow * 1024 + bn;
#pragma unroll
            for (int n = 0; n < 8; n++) {
                int ccl = colb + n * 8;
                float s0 = acc[m * 8 + n][h * 2];
                float s1 = acc[m * 8 + n][h * 2 + 1];
                float4 nv = *(float4*)&nz[rowloc * 128 + ccl];
                float v1a = s0 + nv.x;
                if (v1a > bmax) { bmax2 = bmax; bmax = v1a; bidx = bn + ccl; }
                else if (v1a > bmax2) bmax2 = v1a;
                float v1b = s1 + nv.z;
                if (v1b > bmax) { bmax2 = bmax; bmax = v1b; bidx = bn + ccl + 1; }
                else if (v1b > bmax2) bmax2 = v1b;
                float p0 = __expf(s0) * nv.y;
                float p1 = __expf(s1) * nv.w;
                bsum += p0 + p1;
                *(float2*)(wrow + ccl) = make_float2(p0, p1);
            }
#pragma unroll
            for (int o = 1; o <= 2; o <<= 1) {
                float om  = __shfl_xor_sync(0xffffffffu, bmax, o);
                int   oi  = __shfl_xor_sync(0xffffffffu, bidx, o);
                float om2 = __shfl_xor_sync(0xffffffffu, bmax2, o);
                float os  = __shfl_xor_sync(0xffffffffu, bsum, o);
                float hi2 = fmaxf(fminf(bmax, om), fmaxf(bmax2, om2));
                if (om > bmax || (om == bmax && oi < bidx)) { bmax = om; bidx = oi; }
                bmax2 = hi2;
                bsum += os;
            }
            rmax[e] = bmax; rmax2[e] = bmax2; ridx[e] = bidx; rsum[e] = bsum;
        }

        float* rm  = (float*)(smem);
        int*   ri  = (int*)  (smem + 1024);
        float* rs  = (float*)(smem + 2048);
        float* rm2 = (float*)(smem + 3072);
        if (wn == 1 && (lane & 3) == 0) {
#pragma unroll
            for (int e = 0; e < 4; e++) {
                int rl = wm * 32 + (e >> 1) * 16 + (e & 1) * 8 + g;
                rm[rl] = rmax[e]; ri[rl] = ridx[e]; rs[rl] = rsum[e]; rm2[rl] = rmax2[e];
            }
        }
        __syncthreads();   // join #2
        if (wn == 0 && (lane & 3) == 0) {
#pragma unroll
            for (int e = 0; e < 4; e++) {
                int rl = wm * 32 + (e >> 1) * 16 + (e & 1) * 8 + g;
                float om = rm[rl]; int oi = ri[rl]; float os = rs[rl]; float om2 = rm2[rl];
                float bmv = rmax[e]; int biv = ridx[e];
                float hi2 = fmaxf(fminf(bmv, om), fmaxf(rmax2[e], om2));
                if (om > bmv || (om == bmv && oi < biv)) { bmv = om; biv = oi; }
                size_t pidx = (size_t)(bm + rl) * NBN + blockIdx.x;
                g_pm[pidx] = bmv; g_pi[pidx] = biv;
                g_ps[pidx] = rsum[e] + os; g_p2[pidx] = hi2;
            }
        }
    } else {
        // ================= noise role: 16384 elems, 8 warps, 4x unroll =====
        const int jj = t - 256;   // 0..255
#pragma unroll 4
        for (int it = 0; it < 64; it++) {
            int idx = it * 256 + jj;
            int row = idx >> 7, col = idx & 127;
            uint32_t ctr = (uint32_t)(bm + row) * 1024u + (uint32_t)(bn + col);
            uint32_t b1 = tf_bits(k1a, k1b, ctr);
            float u1 = __uint_as_float((b1 >> 9) | 0x3f800000u) - 1.0f;
            float m1 = -__nv_logf(fmaxf(TINYF, u1 + TINYF));   // precise inner
            float g1 = -__logf(m1);                            // fast outer (TAU+repair)
            uint32_t b2 = tf_bits(k2a, k2b, ctr);
            float u2 = __uint_as_float((b2 >> 9) | 0x3f800000u) - 1.0f;
            float eg = -__fdividef(1.0f, __logf(fmaxf(TINYF, u2 + TINYF))); // fast (R8)
            nz[idx] = make_float2(g1, eg);
        }
        __syncthreads();   // join #1
        __syncthreads();   // join #2
    }
}

// ---------------------------------------------------------------------------
// Kernel 4 (lean): reduce partials; flag rows with gap < TAU into g_rlist;
//   provisional outputs for all rows.
// ---------------------------------------------------------------------------
__global__ void finalize_kernel(const float* __restrict__ cb,
                                float* __restrict__ zq,
                                float* __restrict__ ws,
                                float* __restrict__ idxo) {
    int n = blockIdx.x, t = threadIdx.x;
    __shared__ int   s_best;
    __shared__ float s_inv;
    if (t == 0) {
        float bm = g_pm[(size_t)n * NBN]; int bi = g_pi[(size_t)n * NBN];
        float m2 = g_p2[(size_t)n * NBN];
        float sum = g_ps[(size_t)n * NBN];
#pragma unroll
        for (int j = 1; j < NBN; j++) {
            float m = g_pm[(size_t)n * NBN + j];
            int   i = g_pi[(size_t)n * NBN + j];
            float q2 = g_p2[(size_t)n * NBN + j];
            float hi2 = fmaxf(fminf(bm, m), fmaxf(m2, q2));
            if (m > bm || (m == bm && i < bi)) { bm = m; bi = i; }
            m2 = hi2;
            sum += g_ps[(size_t)n * NBN + j];
        }
        s_best = bi;
        s_inv  = 1.0f / sum;
        if (bm - m2 < TAU) {
            int slot = atomicAdd(&g_rcount, 1);
            g_rlist[slot] = n;
        }
    }
    __syncthreads();
    int best = s_best; float inv = s_inv;

    float4* wrow = (float4*)(ws + (size_t)n * 1024);
    float4 v = wrow[t];
    v.x *= inv; v.y *= inv; v.z *= inv; v.w *= inv;
    wrow[t] = v;

    if (t < 128) {
        float4 c = *(const float4*)(cb + (size_t)best * D_DIM + t * 4);
        *(float4*)(zq + (size_t)n * D_DIM + t * 4) = c;
    }
    if (t == 0) idxo[n] = (float)best;
}

// ---------------------------------------------------------------------------
// Kernel 5: exact repair of flagged rows (fp32 sims + bitwise-exact gumbel).
// ---------------------------------------------------------------------------
__global__ __launch_bounds__(256) void repair_kernel(
        const float* __restrict__ cb,
        float* __restrict__ zq,
        float* __restrict__ idxo,
        uint32_t k1a, uint32_t k1b) {
    __shared__ float xs[512];
    __shared__ float sv8[8];
    __shared__ int   si8[8];
    __shared__ int   s_best;
    int cnt = g_rcount;
    int t = threadIdx.x;
    for (int it = blockIdx.x; it < cnt; it += gridDim.x) {
        int n = g_rlist[it];
        for (int d = t; d < 512; d += 256) xs[d] = g_x[(size_t)n * 512 + d];
        __syncthreads();
        float bv = -3.4e38f; int bi = 0;
#pragma unroll
        for (int v = 0; v < 4; v++) {
            int col = t + v * 256;
            const float4* crow = (const float4*)(g_cn + (size_t)col * 512);
            float s = 0.f;
#pragma unroll 8
            for (int d4 = 0; d4 < 128; d4++) {
                float4 cv = crow[d4];
                s += xs[d4*4]*cv.x + xs[d4*4+1]*cv.y + xs[d4*4+2]*cv.z + xs[d4*4+3]*cv.w;
            }
            float v1 = s + gumbel_exact(
                tf_bits(k1a, k1b, (uint32_t)n * 1024u + (uint32_t)col));
            if (v1 > bv || (v1 == bv && col < bi)) { bv = v1; bi = col; }
        }
        for (int o = 16; o; o >>= 1) {
            float ov = __shfl_down_sync(0xffffffffu, bv, o);
            int   oi = __shfl_down_sync(0xffffffffu, bi, o);
            if (ov > bv || (ov == bv && oi < bi)) { bv = ov; bi = oi; }
        }
        if ((t & 31) == 0) { sv8[t >> 5] = bv; si8[t >> 5] = bi; }
        __syncthreads();
        if (t == 0) {
            float v0 = sv8[0]; int i0 = si8[0];
#pragma unroll
            for (int w = 1; w < 8; w++)
                if (sv8[w] > v0 || (sv8[w] == v0 && si8[w] < i0)) { v0 = sv8[w]; i0 = si8[w]; }
            s_best = i0;
        }
        __syncthreads();
        int best = s_best;
        if (t < 128) {
            float4 c = *(const float4*)(cb + (size_t)best * D_DIM + t * 4);
            *(float4*)(zq + (size_t)n * D_DIM + t * 4) = c;
        }
        if (t == 0) idxo[n] = (float)best;
        __syncthreads();   // protect xs before next row
    }
}

// ---------------------------------------------------------------------------
extern "C" void kernel_launch(void* const* d_in, const int* in_sizes, int n_in,
                              void* d_out, int out_size) {
    const float* st = (const float*)d_in[0];
    const float* ad = (const float*)d_in[1];
    const float* cb = (const float*)d_in[2];
    int N = in_sizes[0] / D_DIM;     // 32768
    int K = in_sizes[2] / D_DIM;     // 1024

    float* out  = (float*)d_out;
    float* zq   = out;                              // [N, D]
    float* ws   = out + (size_t)N * D_DIM;          // [N, K]
    float* idxo = ws + (size_t)N * K;               // [N, 1]

    // jax.random.key(42) -> (0,42); partitionable fold split
    uint32_t g1a = 0u, g1b = 0u;
    threefry2x32(0u, 42u, g1a, g1b);    // counter 0 -> gk1
    uint32_t g2a = 0u, g2b = 1u;
    threefry2x32(0u, 42u, g2a, g2b);    // counter 1 -> gk2

    cudaFuncSetAttribute(gemm_mma,
        cudaFuncAttributeMaxDynamicSharedMemorySize, SMEMB);

    zero_kernel<<<1, 1>>>();
    norm_cb_fp<<<K / 16, 256>>>(cb);
    combine_fp<<<N / 16, 256>>>(st, ad);
    dim3 gg(K / 128, N / 128);          // (8, 256)
    gemm_mma<<<gg, 512, SMEMB>>>(ws, g1a, g1b, g2a, g2b);
    finalize_kernel<<<N, 256>>>(cb, zq, ws, idxo);
    repair_kernel<<<128, 256>>>(cb, zq, idxo, g1a, g1b);
}